// round 9
// baseline (speedup 1.0000x reference)
#include <cuda_runtime.h>
#include <cuda_bf16.h>
#include <cstdint>
#include <math.h>

typedef unsigned int u32;
typedef __nv_bfloat16 bf16;

// Fully-fused NeRF forward. Trunk = bf16x3 split-precision on
// mma.sync.m16n8k16.bf16; L7 + color head = single-pass bf16.
// R9: 512 threads / 16 warps, warp tile 64(M) x 32(N) (2m x 8n grid) for
// 4 warps/SMSP latency hiding; B-fragment software pipeline in nt loop.
// Activations pre-split (hi,lo) bf16; weights staged pre-split transposed.

#define NRF_THREADS 512
#define NRF_TILE    128
#define HSB 264   // h row stride in bf16 (132 words = 4 mod 32: conflict-free)
#define ESB 56    // e row stride in bf16
#define WTS 18    // transposed weight-stage row stride in bf16 (9 words)
#define KC  16    // K rows per staged chunk (= one k16 mma step)

__device__ __forceinline__ void mma16(float* d, const u32* a, const u32* b) {
    asm volatile(
        "mma.sync.aligned.m16n8k16.row.col.f32.bf16.bf16.f32 "
        "{%0,%1,%2,%3}, {%4,%5,%6,%7}, {%8,%9}, {%0,%1,%2,%3};\n"
        : "+f"(d[0]), "+f"(d[1]), "+f"(d[2]), "+f"(d[3])
        : "r"(a[0]), "r"(a[1]), "r"(a[2]), "r"(a[3]),
          "r"(b[0]), "r"(b[1]));
}

__device__ __forceinline__ u32 pack2(bf16 a, bf16 b) {
    __nv_bfloat162 p;
    p.x = a; p.y = b;
    return *reinterpret_cast<u32*>(&p);
}

__device__ __forceinline__ void bsplit(float v, bf16& h, bf16& l) {
    h = __float2bfloat16_rn(v);
    l = __float2bfloat16_rn(v - __bfloat162float(h));
}

// =====================================================================
// bf16x3 K-segment accumulation, warp tile 64x32 over 256 output cols.
// 512-thread staging: scol = tid&255, rows (tid>>8)*8 + j.
// =====================================================================
__device__ __forceinline__ void accum3x_256(
    float acc[4][4][4],
    const float* __restrict__ Wg, int ldw, int co, int kwbase,
    const bf16* __restrict__ src_hi, const bf16* __restrict__ src_lo,
    int sstr, int Kreal,
    bf16* __restrict__ wh0, bf16* __restrict__ wl0,
    bf16* __restrict__ wh1, bf16* __restrict__ wl1,
    int mbase, int n0, int tg, int tq, int tid)
{
    const int Kpad = (Kreal + 15) & ~15;
    const int nch  = Kpad / KC;
    const int scol = tid & 255;
    const int srow = (tid >> 8) * 8;

    #pragma unroll
    for (int j = 0; j < 8; j += 2) {
        const int ka = srow + j;
        const float w0 = (ka     < Kreal) ? Wg[(size_t)(kwbase + ka    ) * ldw + co + scol] : 0.f;
        const float w1 = (ka + 1 < Kreal) ? Wg[(size_t)(kwbase + ka + 1) * ldw + co + scol] : 0.f;
        bf16 h0, l0, h1, l1;
        bsplit(w0, h0, l0);
        bsplit(w1, h1, l1);
        *(u32*)(wh0 + scol * WTS + ka) = pack2(h0, h1);
        *(u32*)(wl0 + scol * WTS + ka) = pack2(l0, l1);
    }
    __syncthreads();

    for (int ci = 0; ci < nch; ci++) {
        bf16* chi = (ci & 1) ? wh1 : wh0;
        bf16* clo = (ci & 1) ? wl1 : wl0;
        bf16* nhi = (ci & 1) ? wh0 : wh1;
        bf16* nlo = (ci & 1) ? wl0 : wl1;
        const int k0 = ci * KC;
        const bool have_next = (ci + 1 < nch);

        float pf[8];
        if (have_next) {
            const int kb = k0 + KC + srow;
            #pragma unroll
            for (int j = 0; j < 8; j++) {
                const int kk = kb + j;
                pf[j] = (kk < Kreal)
                    ? Wg[(size_t)(kwbase + kk) * ldw + co + scol] : 0.f;
            }
        }

        // A fragments (hi/lo) for all 4 m-tiles, resident across nt loop
        u32 ah[4][4], al[4][4];
        #pragma unroll
        for (int mt = 0; mt < 4; mt++) {
            const int r = mbase + mt * 16 + tg;
            const bf16* ph = src_hi + r * sstr + k0 + 2 * tq;
            const bf16* pl = src_lo + r * sstr + k0 + 2 * tq;
            ah[mt][0] = *(const u32*)(ph);
            ah[mt][1] = *(const u32*)(ph + 8 * sstr);
            ah[mt][2] = *(const u32*)(ph + 8);
            ah[mt][3] = *(const u32*)(ph + 8 * sstr + 8);
            al[mt][0] = *(const u32*)(pl);
            al[mt][1] = *(const u32*)(pl + 8 * sstr);
            al[mt][2] = *(const u32*)(pl + 8);
            al[mt][3] = *(const u32*)(pl + 8 * sstr + 8);
        }

        // B-fragment software pipeline over 4 n-tiles
        u32 bh[2], bl[2];
        {
            const bf16* pbh = chi + (n0 + tg) * WTS + 2 * tq;
            const bf16* pbl = clo + (n0 + tg) * WTS + 2 * tq;
            bh[0] = *(const u32*)(pbh);
            bh[1] = *(const u32*)(pbh + 8);
            bl[0] = *(const u32*)(pbl);
            bl[1] = *(const u32*)(pbl + 8);
        }
        #pragma unroll
        for (int nt = 0; nt < 4; nt++) {
            u32 bh_n[2], bl_n[2];
            if (nt < 3) {
                const int nn = n0 + (nt + 1) * 8 + tg;
                const bf16* pbh = chi + nn * WTS + 2 * tq;
                const bf16* pbl = clo + nn * WTS + 2 * tq;
                bh_n[0] = *(const u32*)(pbh);
                bh_n[1] = *(const u32*)(pbh + 8);
                bl_n[0] = *(const u32*)(pbl);
                bl_n[1] = *(const u32*)(pbl + 8);
            }
            #pragma unroll
            for (int mt = 0; mt < 4; mt++) {
                mma16(acc[mt][nt], al[mt], bh);   // Alo*Bhi
                mma16(acc[mt][nt], ah[mt], bl);   // Ahi*Blo
                mma16(acc[mt][nt], ah[mt], bh);   // Ahi*Bhi
            }
            if (nt < 3) {
                bh[0] = bh_n[0]; bh[1] = bh_n[1];
                bl[0] = bl_n[0]; bl[1] = bl_n[1];
            }
        }

        if (have_next) {
            #pragma unroll
            for (int j = 0; j < 8; j += 2) {
                bf16 h0, l0, h1, l1;
                bsplit(pf[j],     h0, l0);
                bsplit(pf[j + 1], h1, l1);
                *(u32*)(nhi + scol * WTS + srow + j) = pack2(h0, h1);
                *(u32*)(nlo + scol * WTS + srow + j) = pack2(l0, l1);
            }
        }
        __syncthreads();
    }
}

// ---- single-pass bf16, warp tile 64x32 over 256 output cols (L7) ----
__device__ __forceinline__ void accum1x_256(
    float acc[4][4][4],
    const float* __restrict__ Wg, int ldw, int co, int kwbase,
    const bf16* __restrict__ src_hi, int sstr, int Kreal,
    bf16* __restrict__ wh0, bf16* __restrict__ wh1,
    int mbase, int n0, int tg, int tq, int tid)
{
    const int Kpad = (Kreal + 15) & ~15;
    const int nch  = Kpad / KC;
    const int scol = tid & 255;
    const int srow = (tid >> 8) * 8;

    #pragma unroll
    for (int j = 0; j < 8; j += 2) {
        const int ka = srow + j;
        const float w0 = (ka     < Kreal) ? Wg[(size_t)(kwbase + ka    ) * ldw + co + scol] : 0.f;
        const float w1 = (ka + 1 < Kreal) ? Wg[(size_t)(kwbase + ka + 1) * ldw + co + scol] : 0.f;
        *(u32*)(wh0 + scol * WTS + ka) =
            pack2(__float2bfloat16_rn(w0), __float2bfloat16_rn(w1));
    }
    __syncthreads();

    for (int ci = 0; ci < nch; ci++) {
        bf16* chi = (ci & 1) ? wh1 : wh0;
        bf16* nhi = (ci & 1) ? wh0 : wh1;
        const int k0 = ci * KC;
        const bool have_next = (ci + 1 < nch);

        float pf[8];
        if (have_next) {
            const int kb = k0 + KC + srow;
            #pragma unroll
            for (int j = 0; j < 8; j++) {
                const int kk = kb + j;
                pf[j] = (kk < Kreal)
                    ? Wg[(size_t)(kwbase + kk) * ldw + co + scol] : 0.f;
            }
        }

        u32 ah[4][4];
        #pragma unroll
        for (int mt = 0; mt < 4; mt++) {
            const int r = mbase + mt * 16 + tg;
            const bf16* ph = src_hi + r * sstr + k0 + 2 * tq;
            ah[mt][0] = *(const u32*)(ph);
            ah[mt][1] = *(const u32*)(ph + 8 * sstr);
            ah[mt][2] = *(const u32*)(ph + 8);
            ah[mt][3] = *(const u32*)(ph + 8 * sstr + 8);
        }

        #pragma unroll
        for (int nt = 0; nt < 4; nt++) {
            const int nn = n0 + nt * 8 + tg;
            const bf16* pbh = chi + nn * WTS + 2 * tq;
            u32 bh[2];
            bh[0] = *(const u32*)(pbh);
            bh[1] = *(const u32*)(pbh + 8);
            #pragma unroll
            for (int mt = 0; mt < 4; mt++)
                mma16(acc[mt][nt], ah[mt], bh);
        }

        if (have_next) {
            #pragma unroll
            for (int j = 0; j < 8; j += 2) {
                *(u32*)(nhi + scol * WTS + srow + j) =
                    pack2(__float2bfloat16_rn(pf[j]), __float2bfloat16_rn(pf[j + 1]));
            }
        }
        __syncthreads();
    }
}

// ---- single-pass bf16, warp tile 64x16 over 128 output cols (head) ----
__device__ __forceinline__ void accum1x_128(
    float acc[4][2][4],
    const float* __restrict__ Wg, int kwbase,
    const bf16* __restrict__ src_hi, int sstr, int Kreal,
    bf16* __restrict__ wh0, bf16* __restrict__ wh1,
    int mbase, int n0, int tg, int tq, int tid)
{
    const int Kpad = (Kreal + 15) & ~15;
    const int nch  = Kpad / KC;
    const int scol = tid & 127;
    const int kh   = (tid >> 7) * 4;   // rows kh..kh+3 of the 16-row chunk

    #pragma unroll
    for (int j = 0; j < 4; j += 2) {
        const int ka = kh + j;
        const float w0 = (ka     < Kreal) ? Wg[(size_t)(kwbase + ka    ) * 128 + scol] : 0.f;
        const float w1 = (ka + 1 < Kreal) ? Wg[(size_t)(kwbase + ka + 1) * 128 + scol] : 0.f;
        *(u32*)(wh0 + scol * WTS + ka) =
            pack2(__float2bfloat16_rn(w0), __float2bfloat16_rn(w1));
    }
    __syncthreads();

    for (int ci = 0; ci < nch; ci++) {
        bf16* chi = (ci & 1) ? wh1 : wh0;
        bf16* nhi = (ci & 1) ? wh0 : wh1;
        const int k0 = ci * KC;
        const bool have_next = (ci + 1 < nch);

        float pf[4];
        if (have_next) {
            const int kb = k0 + KC + kh;
            #pragma unroll
            for (int j = 0; j < 4; j++) {
                const int kk = kb + j;
                pf[j] = (kk < Kreal)
                    ? Wg[(size_t)(kwbase + kk) * 128 + scol] : 0.f;
            }
        }

        u32 ah[4][4];
        #pragma unroll
        for (int mt = 0; mt < 4; mt++) {
            const int r = mbase + mt * 16 + tg;
            const bf16* ph = src_hi + r * sstr + k0 + 2 * tq;
            ah[mt][0] = *(const u32*)(ph);
            ah[mt][1] = *(const u32*)(ph + 8 * sstr);
            ah[mt][2] = *(const u32*)(ph + 8);
            ah[mt][3] = *(const u32*)(ph + 8 * sstr + 8);
        }

        #pragma unroll
        for (int nt = 0; nt < 2; nt++) {
            const int nn = n0 + nt * 8 + tg;
            const bf16* pbh = chi + nn * WTS + 2 * tq;
            u32 bh[2];
            bh[0] = *(const u32*)(pbh);
            bh[1] = *(const u32*)(pbh + 8);
            #pragma unroll
            for (int mt = 0; mt < 4; mt++)
                mma16(acc[mt][nt], ah[mt], bh);
        }

        if (have_next) {
            #pragma unroll
            for (int j = 0; j < 4; j += 2) {
                *(u32*)(nhi + scol * WTS + kh + j) =
                    pack2(__float2bfloat16_rn(pf[j]), __float2bfloat16_rn(pf[j + 1]));
            }
        }
        __syncthreads();
    }
}

// ---- Epilogues: bias + optional ReLU, pre-split hi/lo write to SMEM ----
__device__ __forceinline__ void epilogue_256(
    float acc[4][4][4], const float* __restrict__ bg, int co,
    bf16* __restrict__ dst_hi, bf16* __restrict__ dst_lo, bool relu,
    int mbase, int n0, int tg, int tq)
{
    #pragma unroll
    for (int nt = 0; nt < 4; nt++) {
        const int c = n0 + nt * 8 + 2 * tq;
        const float b0v = bg[co + c];
        const float b1v = bg[co + c + 1];
        #pragma unroll
        for (int mt = 0; mt < 4; mt++) {
            float v0 = acc[mt][nt][0] + b0v;
            float v1 = acc[mt][nt][1] + b1v;
            float v2 = acc[mt][nt][2] + b0v;
            float v3 = acc[mt][nt][3] + b1v;
            if (relu) {
                v0 = fmaxf(v0, 0.f); v1 = fmaxf(v1, 0.f);
                v2 = fmaxf(v2, 0.f); v3 = fmaxf(v3, 0.f);
            }
            const int r = mbase + mt * 16 + tg;
            bf16 h0, l0, h1, l1;
            bsplit(v0, h0, l0); bsplit(v1, h1, l1);
            *(u32*)(dst_hi + r * HSB + c) = pack2(h0, h1);
            *(u32*)(dst_lo + r * HSB + c) = pack2(l0, l1);
            bsplit(v2, h0, l0); bsplit(v3, h1, l1);
            *(u32*)(dst_hi + (r + 8) * HSB + c) = pack2(h0, h1);
            *(u32*)(dst_lo + (r + 8) * HSB + c) = pack2(l0, l1);
        }
    }
}

__device__ __forceinline__ void epilogue_128(
    float acc[4][2][4], const float* __restrict__ bg,
    bf16* __restrict__ dst_hi, bf16* __restrict__ dst_lo,
    int mbase, int n0, int tg, int tq)
{
    #pragma unroll
    for (int nt = 0; nt < 2; nt++) {
        const int c = n0 + nt * 8 + 2 * tq;
        const float b0v = bg[c];
        const float b1v = bg[c + 1];
        #pragma unroll
        for (int mt = 0; mt < 4; mt++) {
            float v0 = fmaxf(acc[mt][nt][0] + b0v, 0.f);
            float v1 = fmaxf(acc[mt][nt][1] + b1v, 0.f);
            float v2 = fmaxf(acc[mt][nt][2] + b0v, 0.f);
            float v3 = fmaxf(acc[mt][nt][3] + b1v, 0.f);
            const int r = mbase + mt * 16 + tg;
            bf16 h0, l0, h1, l1;
            bsplit(v0, h0, l0); bsplit(v1, h1, l1);
            *(u32*)(dst_hi + r * HSB + c) = pack2(h0, h1);
            *(u32*)(dst_lo + r * HSB + c) = pack2(l0, l1);
            bsplit(v2, h0, l0); bsplit(v3, h1, l1);
            *(u32*)(dst_hi + (r + 8) * HSB + c) = pack2(h0, h1);
            *(u32*)(dst_lo + (r + 8) * HSB + c) = pack2(l0, l1);
        }
    }
}

__device__ __forceinline__ void zero_acc4(float acc[4][4][4]) {
    #pragma unroll
    for (int i = 0; i < 4; i++)
        #pragma unroll
        for (int j = 0; j < 4; j++)
            #pragma unroll
            for (int k = 0; k < 4; k++) acc[i][j][k] = 0.f;
}

__global__ void __launch_bounds__(NRF_THREADS, 1) nerf_tc_kernel(
    const float* __restrict__ pts, const float* __restrict__ dirs,
    const float* __restrict__ W0, const float* __restrict__ b0,
    const float* __restrict__ W1, const float* __restrict__ b1,
    const float* __restrict__ W2, const float* __restrict__ b2,
    const float* __restrict__ W3, const float* __restrict__ b3,
    const float* __restrict__ W4, const float* __restrict__ b4,
    const float* __restrict__ W5, const float* __restrict__ b5,
    const float* __restrict__ W6, const float* __restrict__ b6,
    const float* __restrict__ W7, const float* __restrict__ b7,
    const float* __restrict__ Wc, const float* __restrict__ bc,
    const float* __restrict__ Wo, const float* __restrict__ bo,
    float* __restrict__ out_color, float* __restrict__ out_sigma, int P)
{
    extern __shared__ char smc[];
    bf16* h_hi = (bf16*)smc;                    // [128][HSB]
    bf16* h_lo = h_hi + NRF_TILE * HSB;
    bf16* e_hi = h_lo + NRF_TILE * HSB;         // [128][ESB]
    bf16* e_lo = e_hi + NRF_TILE * ESB;
    bf16* wh0  = e_lo + NRF_TILE * ESB;         // [256][WTS] transposed stage
    bf16* wl0  = wh0 + 256 * WTS;
    bf16* wh1  = wl0 + 256 * WTS;
    bf16* wl1  = wh1 + 256 * WTS;

    const int tid  = threadIdx.x;
    const int warp = tid >> 5;
    const int lane = tid & 31;
    const int tg = lane >> 2;
    const int tq = lane & 3;
    const int mbase  = (warp >> 3) * 64;   // 2 m-groups of 64 rows
    const int n0_256 = (warp & 7) * 32;    // 8 n-groups of 32 cols
    const int n0_128 = (warp & 7) * 16;    // 8 n-groups of 16 cols
    const int base = blockIdx.x * NRF_TILE;

    // ---- xyz harmonic embedding, written pre-split (hi/lo bf16) ----
    if (tid < NRF_TILE) {
        const int n = base + tid;
        const float x = pts[n * 3 + 0];
        const float y = pts[n * 3 + 1];
        const float z = pts[n * 3 + 2];
        bf16* eh = e_hi + tid * ESB;
        bf16* el = e_lo + tid * ESB;
        #pragma unroll
        for (int h = 0; h < 6; h++) {
            const float f = (float)(1 << h);
            float sx, cx, sy, cy, sz, cz;
            sincosf(x * f, &sx, &cx);
            sincosf(y * f, &sy, &cy);
            sincosf(z * f, &sz, &cz);
            bf16 hh, ll;
            bsplit(sx, hh, ll); eh[0  + h] = hh; el[0  + h] = ll;
            bsplit(sy, hh, ll); eh[6  + h] = hh; el[6  + h] = ll;
            bsplit(sz, hh, ll); eh[12 + h] = hh; el[12 + h] = ll;
            bsplit(cx, hh, ll); eh[18 + h] = hh; el[18 + h] = ll;
            bsplit(cy, hh, ll); eh[24 + h] = hh; el[24 + h] = ll;
            bsplit(cz, hh, ll); eh[30 + h] = hh; el[30 + h] = ll;
        }
        bf16 hh, ll;
        bsplit(x, hh, ll); eh[36] = hh; el[36] = ll;
        bsplit(y, hh, ll); eh[37] = hh; el[37] = ll;
        bsplit(z, hh, ll); eh[38] = hh; el[38] = ll;
        const bf16 zb = __float2bfloat16_rn(0.f);
        #pragma unroll
        for (int c = 39; c < 48; c++) { eh[c] = zb; el[c] = zb; }
    }
    // (ordered by accum's chunk-0 stage barrier)

    float acc[4][4][4];

    // ---- L0: e(39) -> 256, ReLU (bf16x3) ----
    zero_acc4(acc);
    accum3x_256(acc, W0, 256, 0, 0, e_hi, e_lo, ESB, 39,
                wh0, wl0, wh1, wl1, mbase, n0_256, tg, tq, tid);
    epilogue_256(acc, b0, 0, h_hi, h_lo, true, mbase, n0_256, tg, tq);

    // ---- L1..L4: 256 -> 256, ReLU (bf16x3) ----
    {
        const float* Ws[4] = {W1, W2, W3, W4};
        const float* bs[4] = {b1, b2, b3, b4};
        #pragma unroll 1
        for (int l = 0; l < 4; l++) {
            zero_acc4(acc);
            accum3x_256(acc, Ws[l], 256, 0, 0, h_hi, h_lo, HSB, 256,
                        wh0, wl0, wh1, wl1, mbase, n0_256, tg, tq, tid);
            epilogue_256(acc, bs[l], 0, h_hi, h_lo, true, mbase, n0_256, tg, tq);
        }
    }

    // ---- L5: [h(256), e(39)] -> 256, ReLU (bf16x3) ----
    zero_acc4(acc);
    accum3x_256(acc, W5, 256, 0, 0,   h_hi, h_lo, HSB, 256,
                wh0, wl0, wh1, wl1, mbase, n0_256, tg, tq, tid);
    accum3x_256(acc, W5, 256, 0, 256, e_hi, e_lo, ESB, 39,
                wh0, wl0, wh1, wl1, mbase, n0_256, tg, tq, tid);
    epilogue_256(acc, b5, 0, h_hi, h_lo, true, mbase, n0_256, tg, tq);

    // ---- L6: 256 -> 256, ReLU (bf16x3) ----
    zero_acc4(acc);
    accum3x_256(acc, W6, 256, 0, 0, h_hi, h_lo, HSB, 256,
                wh0, wl0, wh1, wl1, mbase, n0_256, tg, tq, tid);
    epilogue_256(acc, b6, 0, h_hi, h_lo, true, mbase, n0_256, tg, tq);

    __syncthreads();   // h6 fully written before sigma reads whole rows

    // ---- Sigma: col 0 of layer 7, from reconstructed h6 (fp32 SIMT) ----
    if (tid < NRF_TILE) {
        float s = b7[0];
        const bf16* ph = h_hi + tid * HSB;
        const bf16* pl = h_lo + tid * HSB;
        #pragma unroll 4
        for (int k = 0; k < 256; k++) {
            const float hv = __bfloat162float(ph[k]) + __bfloat162float(pl[k]);
            s = fmaf(hv, W7[k * 257], s);
        }
        out_sigma[base + tid] = fmaxf(s, 0.f);
    }
    // (sigma reads finish before L7 epilogue: L7 accum's barriers order them)

    // ---- L7 cols 1..256 (no ReLU, single bf16; A = h_hi) ----
    zero_acc4(acc);
    accum1x_256(acc, W7, 257, 1, 0, h_hi, HSB, 256,
                wh0, wh1, mbase, n0_256, tg, tq, tid);
    epilogue_256(acc, b7, 1, h_hi, h_lo, false, mbase, n0_256, tg, tq);

    // ---- dir harmonic embedding into e arrays (e dead after L5) ----
    if (tid < NRF_TILE) {
        const int n = base + tid;
        const int r = n / P;
        const float dx = dirs[r * 3 + 0];
        const float dy = dirs[r * 3 + 1];
        const float dz = dirs[r * 3 + 2];
        bf16* eh = e_hi + tid * ESB;
        #pragma unroll
        for (int h = 0; h < 4; h++) {
            const float f = (float)(1 << h);
            float sx, cx, sy, cy, sz, cz;
            sincosf(dx * f, &sx, &cx);
            sincosf(dy * f, &sy, &cy);
            sincosf(dz * f, &sz, &cz);
            eh[0  + h] = __float2bfloat16_rn(sx);
            eh[4  + h] = __float2bfloat16_rn(sy);
            eh[8  + h] = __float2bfloat16_rn(sz);
            eh[12 + h] = __float2bfloat16_rn(cx);
            eh[16 + h] = __float2bfloat16_rn(cy);
            eh[20 + h] = __float2bfloat16_rn(cz);
        }
        eh[24] = __float2bfloat16_rn(dx);
        eh[25] = __float2bfloat16_rn(dy);
        eh[26] = __float2bfloat16_rn(dz);
        const bf16 zb = __float2bfloat16_rn(0.f);
        #pragma unroll
        for (int c = 27; c < 32; c++) eh[c] = zb;
    }
    // (ordered before use by head accum's stage barrier)

    // ---- Color head: [h7(256), d(27)] -> 128, ReLU (single bf16) ----
    {
        float acc2[4][2][4];
        #pragma unroll
        for (int i = 0; i < 4; i++)
            #pragma unroll
            for (int j = 0; j < 2; j++)
                #pragma unroll
                for (int k = 0; k < 4; k++) acc2[i][j][k] = 0.f;
        accum1x_128(acc2, Wc, 0,   h_hi, HSB, 256,
                    wh0, wh1, mbase, n0_128, tg, tq, tid);
        accum1x_128(acc2, Wc, 256, e_hi, ESB, 27,
                    wh0, wh1, mbase, n0_128, tg, tq, tid);
        epilogue_128(acc2, bc, h_hi, h_lo, mbase, n0_128, tg, tq);
    }

    __syncthreads();   // head output fully written before final reads

    // ---- Output: sigmoid(h @ Wo + bo), 3 cols per point (384 pairs) ----
    if (tid < NRF_TILE * 3) {
        const int p = tid / 3;
        const int c = tid - p * 3;
        float s = bo[c];
        const bf16* ph = h_hi + p * HSB;
        const bf16* pl = h_lo + p * HSB;
        #pragma unroll 4
        for (int k = 0; k < 128; k++) {
            const float hv = __bfloat162float(ph[k]) + __bfloat162float(pl[k]);
            s = fmaf(hv, Wo[k * 3 + c], s);
        }
        out_color[(base + p) * 3 + c] = 1.f / (1.f + expf(-s));
    }
}

extern "C" void kernel_launch(void* const* d_in, const int* in_sizes, int n_in,
                              void* d_out, int out_size)
{
    const float* pts  = (const float*)d_in[0];
    const float* dirs = (const float*)d_in[1];
    const float* W0 = (const float*)d_in[2];   const float* b0 = (const float*)d_in[3];
    const float* W1 = (const float*)d_in[4];   const float* b1 = (const float*)d_in[5];
    const float* W2 = (const float*)d_in[6];   const float* b2 = (const float*)d_in[7];
    const float* W3 = (const float*)d_in[8];   const float* b3 = (const float*)d_in[9];
    const float* W4 = (const float*)d_in[10];  const float* b4 = (const float*)d_in[11];
    const float* W5 = (const float*)d_in[12];  const float* b5 = (const float*)d_in[13];
    const float* W6 = (const float*)d_in[14];  const float* b6 = (const float*)d_in[15];
    const float* W7 = (const float*)d_in[16];  const float* b7 = (const float*)d_in[17];
    const float* Wc = (const float*)d_in[18];  const float* bc = (const float*)d_in[19];
    const float* Wo = (const float*)d_in[20];  const float* bo = (const float*)d_in[21];

    const int N = in_sizes[0] / 3;        // 131072 points
    const int R = in_sizes[1] / 3;        // 2048 rays
    const int P = N / R;                  // 64 samples per ray

    float* out_color = (float*)d_out;               // [N,3] first (tuple order)
    float* out_sigma = out_color + (size_t)N * 3;   // [N,1] after

    const int smem_bytes = (NRF_TILE * HSB * 2 + NRF_TILE * ESB * 2 +
                            256 * WTS * 4) * (int)sizeof(bf16);
    cudaFuncSetAttribute(nerf_tc_kernel,
                         cudaFuncAttributeMaxDynamicSharedMemorySize, smem_bytes);

    nerf_tc_kernel<<<N / NRF_TILE, NRF_THREADS, smem_bytes>>>(
        pts, dirs,
        W0, b0, W1, b1, W2, b2, W3, b3, W4, b4, W5, b5, W6, b6, W7, b7,
        Wc, bc, Wo, bo,
        out_color, out_sigma, P);
}

// round 10
// speedup vs baseline: 1.4872x; 1.4872x over previous
#include <cuda_runtime.h>
#include <cuda_bf16.h>
#include <cstdint>
#include <math.h>

typedef unsigned int u32;
typedef __nv_bfloat16 bf16;

// R10: two-kernel design.
//  prep_weights: packs all layer weights into g_wscr as ready-to-load mma
//    B-fragments (bf16 hi/lo split, lane-ordered so a fragment = one LDG.128
//    for 3x trunk layers / LDG.64 for 1x layers). Runs once per launch.
//  nerf_tc_kernel: fully-fused forward; B-frags LDG'd from L2, A-frags from
//    SMEM activations. No weight staging => barriers drop from ~340 to ~22.
// 512 threads / 16 warps, warp tile 64(M) x 32(N). bf16x3 trunk, 1x heads.

#define NRF_THREADS 512
#define NRF_TILE    128
#define HSB 264   // h row stride in bf16 (132 words = 4 mod 32: conflict-free)
#define ESB 56    // e row stride in bf16

// ---- scratch segment table (u32 offsets) ----
// seg: 0=W0 1=W1 2=W2 3=W3 4=W4 5=W5(h) 6=W5(e) 7=W6   [3x, uint4/lane]
//      8=W7 9=Wc(h) 10=Wc(e)                           [1x, uint2/lane]
#define OFF_W0   0
#define OFF_W1   12288
#define OFF_W2   77824
#define OFF_W3   143360
#define OFF_W4   208896
#define OFF_W5H  274432
#define OFF_W5E  339968
#define OFF_W6   352256
#define OFF_W7   417792
#define OFF_WCH  450560
#define OFF_WCE  466944
#define SCR_TOTAL 468992
#define PREP_ELEMS 130048

__device__ __align__(16) u32 g_wscr[SCR_TOTAL];

__device__ __forceinline__ void mma16(float* d, const u32* a, const u32* b) {
    asm volatile(
        "mma.sync.aligned.m16n8k16.row.col.f32.bf16.bf16.f32 "
        "{%0,%1,%2,%3}, {%4,%5,%6,%7}, {%8,%9}, {%0,%1,%2,%3};\n"
        : "+f"(d[0]), "+f"(d[1]), "+f"(d[2]), "+f"(d[3])
        : "r"(a[0]), "r"(a[1]), "r"(a[2]), "r"(a[3]),
          "r"(b[0]), "r"(b[1]));
}

__device__ __forceinline__ u32 pack2(bf16 a, bf16 b) {
    __nv_bfloat162 p;
    p.x = a; p.y = b;
    return *reinterpret_cast<u32*>(&p);
}

__device__ __forceinline__ void bsplit(float v, bf16& h, bf16& l) {
    h = __float2bfloat16_rn(v);
    l = __float2bfloat16_rn(v - __bfloat162float(h));
}

// =====================================================================
// Pre-pass: build B-fragment scratch. One thread per (seg,chunk,ntile,lane).
// =====================================================================
#define NSEG 11
__global__ void prep_weights(
    const float* __restrict__ W0, const float* __restrict__ W1,
    const float* __restrict__ W2, const float* __restrict__ W3,
    const float* __restrict__ W4, const float* __restrict__ W5,
    const float* __restrict__ W6, const float* __restrict__ W7,
    const float* __restrict__ Wc)
{
    const int nch[NSEG] = {3,16,16,16,16,16,3,16,16,16,2};
    const int ntl[NSEG] = {32,32,32,32,32,32,32,32,32,16,16};
    const int is3[NSEG] = {1,1,1,1,1,1,1,1,0,0,0};
    const int ldw[NSEG] = {256,256,256,256,256,256,256,256,257,128,128};
    const int cof[NSEG] = {0,0,0,0,0,0,0,0,1,0,0};
    const int kwb[NSEG] = {0,0,0,0,0,0,256,0,0,0,256};
    const int kre[NSEG] = {39,256,256,256,256,256,39,256,256,256,27};
    const int off[NSEG] = {OFF_W0,OFF_W1,OFF_W2,OFF_W3,OFF_W4,OFF_W5H,
                           OFF_W5E,OFF_W6,OFF_W7,OFF_WCH,OFF_WCE};
    const float* Wp[NSEG] = {W0,W1,W2,W3,W4,W5,W5,W6,W7,Wc,Wc};

    int gid = blockIdx.x * blockDim.x + threadIdx.x;
    if (gid >= PREP_ELEMS) return;

    int seg = 0, acc = 0;
    for (int s = 0; s < NSEG; s++) {
        const int cnt = nch[s] * ntl[s] * 32;
        if (gid < acc + cnt) { seg = s; break; }
        acc += cnt;
    }
    int rem = gid - acc;
    const int lane  = rem & 31;  rem >>= 5;
    const int ntile = rem % ntl[seg];
    const int ci    = rem / ntl[seg];
    const int tg = lane >> 2, tq = lane & 3;
    const int col = cof[seg] + ntile * 8 + tg;
    const int k0  = ci * 16;
    const float* W = Wp[seg];
    const int ld = ldw[seg], kb = kwb[seg], KR = kre[seg];

    const float wA = (k0 + 2*tq     < KR) ? W[(size_t)(kb + k0 + 2*tq    ) * ld + col] : 0.f;
    const float wB = (k0 + 2*tq + 1 < KR) ? W[(size_t)(kb + k0 + 2*tq + 1) * ld + col] : 0.f;
    const float wC = (k0 + 8 + 2*tq     < KR) ? W[(size_t)(kb + k0 + 8 + 2*tq    ) * ld + col] : 0.f;
    const float wD = (k0 + 8 + 2*tq + 1 < KR) ? W[(size_t)(kb + k0 + 8 + 2*tq + 1) * ld + col] : 0.f;
    bf16 hA,lA,hB,lB,hC,lC,hD,lD;
    bsplit(wA,hA,lA); bsplit(wB,hB,lB); bsplit(wC,hC,lC); bsplit(wD,hD,lD);

    if (is3[seg]) {
        u32* p = g_wscr + off[seg] + ci * (ntl[seg] * 128) + ntile * 128 + lane * 4;
        p[0] = pack2(hA,hB); p[1] = pack2(hC,hD);
        p[2] = pack2(lA,lB); p[3] = pack2(lC,lD);
    } else {
        u32* p = g_wscr + off[seg] + ci * (ntl[seg] * 64) + ntile * 64 + lane * 2;
        p[0] = pack2(hA,hB); p[1] = pack2(hC,hD);
    }
}

// =====================================================================
// bf16x3 accumulation, B-frags direct from scratch (uint4 per lane/ntile).
// No barriers inside.
// =====================================================================
__device__ __forceinline__ void accum3x_g(
    float acc[4][4][4], const u32* __restrict__ segp, int nch,
    const bf16* __restrict__ src_hi, const bf16* __restrict__ src_lo,
    int sstr, int mbase, int n0, int tg, int tq, int lane)
{
    const uint4* wb = reinterpret_cast<const uint4*>(segp) + (n0 >> 3) * 32 + lane;
    for (int ci = 0; ci < nch; ci++) {
        const uint4* pc = wb + ci * 1024;          // chunk stride 4096 u32
        uint4 B0 = __ldg(pc);
        uint4 B1 = __ldg(pc + 32);
        uint4 B2 = __ldg(pc + 64);
        uint4 B3 = __ldg(pc + 96);
        const int k0 = ci * 16;
        u32 ah[4][4], al[4][4];
        #pragma unroll
        for (int mt = 0; mt < 4; mt++) {
            const int r = mbase + mt * 16 + tg;
            const bf16* ph = src_hi + r * sstr + k0 + 2 * tq;
            const bf16* pl = src_lo + r * sstr + k0 + 2 * tq;
            ah[mt][0] = *(const u32*)(ph);
            ah[mt][1] = *(const u32*)(ph + 8 * sstr);
            ah[mt][2] = *(const u32*)(ph + 8);
            ah[mt][3] = *(const u32*)(ph + 8 * sstr + 8);
            al[mt][0] = *(const u32*)(pl);
            al[mt][1] = *(const u32*)(pl + 8 * sstr);
            al[mt][2] = *(const u32*)(pl + 8);
            al[mt][3] = *(const u32*)(pl + 8 * sstr + 8);
        }
        uint4 Bv[4] = {B0, B1, B2, B3};
        #pragma unroll
        for (int nt = 0; nt < 4; nt++) {
            const u32 bh[2] = {Bv[nt].x, Bv[nt].y};
            const u32 bl[2] = {Bv[nt].z, Bv[nt].w};
            #pragma unroll
            for (int mt = 0; mt < 4; mt++) {
                mma16(acc[mt][nt], al[mt], bh);   // Alo*Bhi
                mma16(acc[mt][nt], ah[mt], bl);   // Ahi*Blo
                mma16(acc[mt][nt], ah[mt], bh);   // Ahi*Bhi
            }
        }
    }
}

// ---- single-pass bf16, 256 cols (L7): uint2 B-frags ----
__device__ __forceinline__ void accum1x_g256(
    float acc[4][4][4], const u32* __restrict__ segp, int nch,
    const bf16* __restrict__ src_hi, int sstr,
    int mbase, int n0, int tg, int tq, int lane)
{
    const uint2* wb = reinterpret_cast<const uint2*>(segp) + (n0 >> 3) * 32 + lane;
    for (int ci = 0; ci < nch; ci++) {
        const uint2* pc = wb + ci * 1024;          // chunk stride 2048 u32
        uint2 B0 = __ldg(pc);
        uint2 B1 = __ldg(pc + 32);
        uint2 B2 = __ldg(pc + 64);
        uint2 B3 = __ldg(pc + 96);
        const int k0 = ci * 16;
        u32 ah[4][4];
        #pragma unroll
        for (int mt = 0; mt < 4; mt++) {
            const int r = mbase + mt * 16 + tg;
            const bf16* ph = src_hi + r * sstr + k0 + 2 * tq;
            ah[mt][0] = *(const u32*)(ph);
            ah[mt][1] = *(const u32*)(ph + 8 * sstr);
            ah[mt][2] = *(const u32*)(ph + 8);
            ah[mt][3] = *(const u32*)(ph + 8 * sstr + 8);
        }
        uint2 Bv[4] = {B0, B1, B2, B3};
        #pragma unroll
        for (int nt = 0; nt < 4; nt++) {
            const u32 bh[2] = {Bv[nt].x, Bv[nt].y};
            #pragma unroll
            for (int mt = 0; mt < 4; mt++)
                mma16(acc[mt][nt], ah[mt], bh);
        }
    }
}

// ---- single-pass bf16, 128 cols (head): 2 ntiles per warp ----
__device__ __forceinline__ void accum1x_g128(
    float acc[4][2][4], const u32* __restrict__ segp, int nch,
    const bf16* __restrict__ src_hi, int sstr,
    int mbase, int n0, int tg, int tq, int lane)
{
    const uint2* wb = reinterpret_cast<const uint2*>(segp) + (n0 >> 3) * 32 + lane;
    for (int ci = 0; ci < nch; ci++) {
        const uint2* pc = wb + ci * 512;           // chunk stride 1024 u32
        uint2 B0 = __ldg(pc);
        uint2 B1 = __ldg(pc + 32);
        const int k0 = ci * 16;
        u32 ah[4][4];
        #pragma unroll
        for (int mt = 0; mt < 4; mt++) {
            const int r = mbase + mt * 16 + tg;
            const bf16* ph = src_hi + r * sstr + k0 + 2 * tq;
            ah[mt][0] = *(const u32*)(ph);
            ah[mt][1] = *(const u32*)(ph + 8 * sstr);
            ah[mt][2] = *(const u32*)(ph + 8);
            ah[mt][3] = *(const u32*)(ph + 8 * sstr + 8);
        }
        uint2 Bv[2] = {B0, B1};
        #pragma unroll
        for (int nt = 0; nt < 2; nt++) {
            const u32 bh[2] = {Bv[nt].x, Bv[nt].y};
            #pragma unroll
            for (int mt = 0; mt < 4; mt++)
                mma16(acc[mt][nt], ah[mt], bh);
        }
    }
}

// ---- Epilogues: barrier, bias+ReLU, pre-split write, barrier ----
__device__ __forceinline__ void epilogue_256(
    float acc[4][4][4], const float* __restrict__ bg, int co,
    bf16* __restrict__ dst_hi, bf16* __restrict__ dst_lo, bool relu,
    int mbase, int n0, int tg, int tq)
{
    __syncthreads();   // all A-reads of previous buffer complete
    #pragma unroll
    for (int nt = 0; nt < 4; nt++) {
        const int c = n0 + nt * 8 + 2 * tq;
        const float b0v = bg[co + c];
        const float b1v = bg[co + c + 1];
        #pragma unroll
        for (int mt = 0; mt < 4; mt++) {
            float v0 = acc[mt][nt][0] + b0v;
            float v1 = acc[mt][nt][1] + b1v;
            float v2 = acc[mt][nt][2] + b0v;
            float v3 = acc[mt][nt][3] + b1v;
            if (relu) {
                v0 = fmaxf(v0, 0.f); v1 = fmaxf(v1, 0.f);
                v2 = fmaxf(v2, 0.f); v3 = fmaxf(v3, 0.f);
            }
            const int r = mbase + mt * 16 + tg;
            bf16 h0, l0, h1, l1;
            bsplit(v0, h0, l0); bsplit(v1, h1, l1);
            *(u32*)(dst_hi + r * HSB + c) = pack2(h0, h1);
            *(u32*)(dst_lo + r * HSB + c) = pack2(l0, l1);
            bsplit(v2, h0, l0); bsplit(v3, h1, l1);
            *(u32*)(dst_hi + (r + 8) * HSB + c) = pack2(h0, h1);
            *(u32*)(dst_lo + (r + 8) * HSB + c) = pack2(l0, l1);
        }
    }
    __syncthreads();   // writes visible before next layer reads
}

__device__ __forceinline__ void epilogue_128(
    float acc[4][2][4], const float* __restrict__ bg,
    bf16* __restrict__ dst_hi, bf16* __restrict__ dst_lo,
    int mbase, int n0, int tg, int tq)
{
    __syncthreads();
    #pragma unroll
    for (int nt = 0; nt < 2; nt++) {
        const int c = n0 + nt * 8 + 2 * tq;
        const float b0v = bg[c];
        const float b1v = bg[c + 1];
        #pragma unroll
        for (int mt = 0; mt < 4; mt++) {
            float v0 = fmaxf(acc[mt][nt][0] + b0v, 0.f);
            float v1 = fmaxf(acc[mt][nt][1] + b1v, 0.f);
            float v2 = fmaxf(acc[mt][nt][2] + b0v, 0.f);
            float v3 = fmaxf(acc[mt][nt][3] + b1v, 0.f);
            const int r = mbase + mt * 16 + tg;
            bf16 h0, l0, h1, l1;
            bsplit(v0, h0, l0); bsplit(v1, h1, l1);
            *(u32*)(dst_hi + r * HSB + c) = pack2(h0, h1);
            *(u32*)(dst_lo + r * HSB + c) = pack2(l0, l1);
            bsplit(v2, h0, l0); bsplit(v3, h1, l1);
            *(u32*)(dst_hi + (r + 8) * HSB + c) = pack2(h0, h1);
            *(u32*)(dst_lo + (r + 8) * HSB + c) = pack2(l0, l1);
        }
    }
    __syncthreads();
}

__device__ __forceinline__ void zero_acc4(float acc[4][4][4]) {
    #pragma unroll
    for (int i = 0; i < 4; i++)
        #pragma unroll
        for (int j = 0; j < 4; j++)
            #pragma unroll
            for (int k = 0; k < 4; k++) acc[i][j][k] = 0.f;
}

__global__ void __launch_bounds__(NRF_THREADS, 1) nerf_tc_kernel(
    const float* __restrict__ pts, const float* __restrict__ dirs,
    const float* __restrict__ b0, const float* __restrict__ b1,
    const float* __restrict__ b2, const float* __restrict__ b3,
    const float* __restrict__ b4, const float* __restrict__ b5,
    const float* __restrict__ b6, const float* __restrict__ b7,
    const float* __restrict__ W7, const float* __restrict__ bc,
    const float* __restrict__ Wo, const float* __restrict__ bo,
    float* __restrict__ out_color, float* __restrict__ out_sigma, int P)
{
    extern __shared__ char smc[];
    bf16* h_hi = (bf16*)smc;                    // [128][HSB]
    bf16* h_lo = h_hi + NRF_TILE * HSB;
    bf16* e_hi = h_lo + NRF_TILE * HSB;         // [128][ESB]
    bf16* e_lo = e_hi + NRF_TILE * ESB;

    const int tid  = threadIdx.x;
    const int warp = tid >> 5;
    const int lane = tid & 31;
    const int tg = lane >> 2;
    const int tq = lane & 3;
    const int mbase  = (warp >> 3) * 64;   // 2 m-groups of 64 rows
    const int n0_256 = (warp & 7) * 32;    // 8 n-groups of 32 cols
    const int n0_128 = (warp & 7) * 16;    // 8 n-groups of 16 cols
    const int base = blockIdx.x * NRF_TILE;

    // ---- xyz harmonic embedding, pre-split hi/lo ----
    if (tid < NRF_TILE) {
        const int n = base + tid;
        const float x = pts[n * 3 + 0];
        const float y = pts[n * 3 + 1];
        const float z = pts[n * 3 + 2];
        bf16* eh = e_hi + tid * ESB;
        bf16* el = e_lo + tid * ESB;
        #pragma unroll
        for (int h = 0; h < 6; h++) {
            const float f = (float)(1 << h);
            float sx, cx, sy, cy, sz, cz;
            sincosf(x * f, &sx, &cx);
            sincosf(y * f, &sy, &cy);
            sincosf(z * f, &sz, &cz);
            bf16 hh, ll;
            bsplit(sx, hh, ll); eh[0  + h] = hh; el[0  + h] = ll;
            bsplit(sy, hh, ll); eh[6  + h] = hh; el[6  + h] = ll;
            bsplit(sz, hh, ll); eh[12 + h] = hh; el[12 + h] = ll;
            bsplit(cx, hh, ll); eh[18 + h] = hh; el[18 + h] = ll;
            bsplit(cy, hh, ll); eh[24 + h] = hh; el[24 + h] = ll;
            bsplit(cz, hh, ll); eh[30 + h] = hh; el[30 + h] = ll;
        }
        bf16 hh, ll;
        bsplit(x, hh, ll); eh[36] = hh; el[36] = ll;
        bsplit(y, hh, ll); eh[37] = hh; el[37] = ll;
        bsplit(z, hh, ll); eh[38] = hh; el[38] = ll;
        const bf16 zb = __float2bfloat16_rn(0.f);
        #pragma unroll
        for (int c = 39; c < 48; c++) { eh[c] = zb; el[c] = zb; }
    }
    __syncthreads();

    float acc[4][4][4];

    // ---- L0: e(39) -> 256, ReLU ----
    zero_acc4(acc);
    accum3x_g(acc, g_wscr + OFF_W0, 3, e_hi, e_lo, ESB, mbase, n0_256, tg, tq, lane);
    epilogue_256(acc, b0, 0, h_hi, h_lo, true, mbase, n0_256, tg, tq);

    // ---- L1..L4 ----
    {
        const u32* segs[4] = {g_wscr + OFF_W1, g_wscr + OFF_W2,
                              g_wscr + OFF_W3, g_wscr + OFF_W4};
        const float* bs[4] = {b1, b2, b3, b4};
        #pragma unroll 1
        for (int l = 0; l < 4; l++) {
            zero_acc4(acc);
            accum3x_g(acc, segs[l], 16, h_hi, h_lo, HSB, mbase, n0_256, tg, tq, lane);
            epilogue_256(acc, bs[l], 0, h_hi, h_lo, true, mbase, n0_256, tg, tq);
        }
    }

    // ---- L5: [h, e] ----
    zero_acc4(acc);
    accum3x_g(acc, g_wscr + OFF_W5H, 16, h_hi, h_lo, HSB, mbase, n0_256, tg, tq, lane);
    accum3x_g(acc, g_wscr + OFF_W5E, 3,  e_hi, e_lo, ESB, mbase, n0_256, tg, tq, lane);
    epilogue_256(acc, b5, 0, h_hi, h_lo, true, mbase, n0_256, tg, tq);

    // ---- L6 ----
    zero_acc4(acc);
    accum3x_g(acc, g_wscr + OFF_W6, 16, h_hi, h_lo, HSB, mbase, n0_256, tg, tq, lane);
    epilogue_256(acc, b6, 0, h_hi, h_lo, true, mbase, n0_256, tg, tq);

    // ---- Sigma (fp32 SIMT over reconstructed h6) ----
    if (tid < NRF_TILE) {
        float s = b7[0];
        const bf16* ph = h_hi + tid * HSB;
        const bf16* pl = h_lo + tid * HSB;
        #pragma unroll 4
        for (int k = 0; k < 256; k++) {
            const float hv = __bfloat162float(ph[k]) + __bfloat162float(pl[k]);
            s = fmaf(hv, W7[k * 257], s);
        }
        out_sigma[base + tid] = fmaxf(s, 0.f);
    }

    // ---- L7 cols 1..256 (1x bf16) ----
    zero_acc4(acc);
    accum1x_g256(acc, g_wscr + OFF_W7, 16, h_hi, HSB, mbase, n0_256, tg, tq, lane);
    epilogue_256(acc, b7, 1, h_hi, h_lo, false, mbase, n0_256, tg, tq);

    // ---- dir harmonic embedding (reuses e_hi) ----
    if (tid < NRF_TILE) {
        const int n = base + tid;
        const int r = n / P;
        const float dx = dirs[r * 3 + 0];
        const float dy = dirs[r * 3 + 1];
        const float dz = dirs[r * 3 + 2];
        bf16* eh = e_hi + tid * ESB;
        #pragma unroll
        for (int h = 0; h < 4; h++) {
            const float f = (float)(1 << h);
            float sx, cx, sy, cy, sz, cz;
            sincosf(dx * f, &sx, &cx);
            sincosf(dy * f, &sy, &cy);
            sincosf(dz * f, &sz, &cz);
            eh[0  + h] = __float2bfloat16_rn(sx);
            eh[4  + h] = __float2bfloat16_rn(sy);
            eh[8  + h] = __float2bfloat16_rn(sz);
            eh[12 + h] = __float2bfloat16_rn(cx);
            eh[16 + h] = __float2bfloat16_rn(cy);
            eh[20 + h] = __float2bfloat16_rn(cz);
        }
        eh[24] = __float2bfloat16_rn(dx);
        eh[25] = __float2bfloat16_rn(dy);
        eh[26] = __float2bfloat16_rn(dz);
        const bf16 zb = __float2bfloat16_rn(0.f);
        #pragma unroll
        for (int c = 27; c < 32; c++) eh[c] = zb;
    }
    __syncthreads();

    // ---- Color head: [h7, d] -> 128, ReLU ----
    {
        float acc2[4][2][4];
        #pragma unroll
        for (int i = 0; i < 4; i++)
            #pragma unroll
            for (int j = 0; j < 2; j++)
                #pragma unroll
                for (int k = 0; k < 4; k++) acc2[i][j][k] = 0.f;
        accum1x_g128(acc2, g_wscr + OFF_WCH, 16, h_hi, HSB, mbase, n0_128, tg, tq, lane);
        accum1x_g128(acc2, g_wscr + OFF_WCE, 2,  e_hi, ESB, mbase, n0_128, tg, tq, lane);
        epilogue_128(acc2, bc, h_hi, h_lo, mbase, n0_128, tg, tq);
    }

    // ---- Output: sigmoid(h @ Wo + bo) ----
    if (tid < NRF_TILE * 3) {
        const int p = tid / 3;
        const int c = tid - p * 3;
        float s = bo[c];
        const bf16* ph = h_hi + p * HSB;
        const bf16* pl = h_lo + p * HSB;
        #pragma unroll 4
        for (int k = 0; k < 128; k++) {
            const float hv = __bfloat162float(ph[k]) + __bfloat162float(pl[k]);
            s = fmaf(hv, Wo[k * 3 + c], s);
        }
        out_color[(base + p) * 3 + c] = 1.f / (1.f + expf(-s));
    }
}

extern "C" void kernel_launch(void* const* d_in, const int* in_sizes, int n_in,
                              void* d_out, int out_size)
{
    const float* pts  = (const float*)d_in[0];
    const float* dirs = (const float*)d_in[1];
    const float* W0 = (const float*)d_in[2];   const float* b0 = (const float*)d_in[3];
    const float* W1 = (const float*)d_in[4];   const float* b1 = (const float*)d_in[5];
    const float* W2 = (const float*)d_in[6];   const float* b2 = (const float*)d_in[7];
    const float* W3 = (const float*)d_in[8];   const float* b3 = (const float*)d_in[9];
    const float* W4 = (const float*)d_in[10];  const float* b4 = (const float*)d_in[11];
    const float* W5 = (const float*)d_in[12];  const float* b5 = (const float*)d_in[13];
    const float* W6 = (const float*)d_in[14];  const float* b6 = (const float*)d_in[15];
    const float* W7 = (const float*)d_in[16];  const float* b7 = (const float*)d_in[17];
    const float* Wc = (const float*)d_in[18];  const float* bc = (const float*)d_in[19];
    const float* Wo = (const float*)d_in[20];  const float* bo = (const float*)d_in[21];

    const int N = in_sizes[0] / 3;        // 131072 points
    const int R = in_sizes[1] / 3;        // 2048 rays
    const int P = N / R;                  // 64 samples per ray

    float* out_color = (float*)d_out;               // [N,3] first (tuple order)
    float* out_sigma = out_color + (size_t)N * 3;   // [N,1] after

    prep_weights<<<(PREP_ELEMS + 255) / 256, 256>>>(
        W0, W1, W2, W3, W4, W5, W6, W7, Wc);

    const int smem_bytes = (NRF_TILE * HSB * 2 + NRF_TILE * ESB * 2)
                           * (int)sizeof(bf16);
    cudaFuncSetAttribute(nerf_tc_kernel,
                         cudaFuncAttributeMaxDynamicSharedMemorySize, smem_bytes);

    nerf_tc_kernel<<<N / NRF_TILE, NRF_THREADS, smem_bytes>>>(
        pts, dirs,
        b0, b1, b2, b3, b4, b5, b6, b7,
        W7, bc, Wo, bo,
        out_color, out_sigma, P);
}

// round 11
// speedup vs baseline: 1.6425x; 1.1044x over previous
#include <cuda_runtime.h>
#include <cuda_bf16.h>
#include <cstdint>
#include <math.h>

typedef unsigned int u32;
typedef __nv_bfloat16 bf16;

// R11: TILE=64 / 256 threads / 2 CTAs per SM (desynchronized epilogues keep
// the tensor pipe fed across layer boundaries); term-outer mma ordering over
// nt-pairs (acc RAW reuse distance 4). Same bf16x3 trunk + 1x heads, same
// prep_weights scratch as R10.

#define NRF_THREADS 256
#define NRF_TILE    64
#define HSB 264   // h row stride in bf16 (132 u32 = 4 mod 32: conflict-free)
#define ESB 56    // e row stride in bf16 (28 u32: conflict-free)

// ---- scratch segment table (u32 offsets), identical to R10 ----
#define OFF_W0   0
#define OFF_W1   12288
#define OFF_W2   77824
#define OFF_W3   143360
#define OFF_W4   208896
#define OFF_W5H  274432
#define OFF_W5E  339968
#define OFF_W6   352256
#define OFF_W7   417792
#define OFF_WCH  450560
#define OFF_WCE  466944
#define SCR_TOTAL 468992
#define PREP_ELEMS 130048

__device__ __align__(16) u32 g_wscr[SCR_TOTAL];

__device__ __forceinline__ void mma16(float* d, const u32* a, const u32* b) {
    asm volatile(
        "mma.sync.aligned.m16n8k16.row.col.f32.bf16.bf16.f32 "
        "{%0,%1,%2,%3}, {%4,%5,%6,%7}, {%8,%9}, {%0,%1,%2,%3};\n"
        : "+f"(d[0]), "+f"(d[1]), "+f"(d[2]), "+f"(d[3])
        : "r"(a[0]), "r"(a[1]), "r"(a[2]), "r"(a[3]),
          "r"(b[0]), "r"(b[1]));
}

__device__ __forceinline__ u32 pack2(bf16 a, bf16 b) {
    __nv_bfloat162 p;
    p.x = a; p.y = b;
    return *reinterpret_cast<u32*>(&p);
}

__device__ __forceinline__ void bsplit(float v, bf16& h, bf16& l) {
    h = __float2bfloat16_rn(v);
    l = __float2bfloat16_rn(v - __bfloat162float(h));
}

// =====================================================================
// Pre-pass: build B-fragment scratch (identical to R10).
// =====================================================================
#define NSEG 11
__global__ void prep_weights(
    const float* __restrict__ W0, const float* __restrict__ W1,
    const float* __restrict__ W2, const float* __restrict__ W3,
    const float* __restrict__ W4, const float* __restrict__ W5,
    const float* __restrict__ W6, const float* __restrict__ W7,
    const float* __restrict__ Wc)
{
    const int nch[NSEG] = {3,16,16,16,16,16,3,16,16,16,2};
    const int ntl[NSEG] = {32,32,32,32,32,32,32,32,32,16,16};
    const int is3[NSEG] = {1,1,1,1,1,1,1,1,0,0,0};
    const int ldw[NSEG] = {256,256,256,256,256,256,256,256,257,128,128};
    const int cof[NSEG] = {0,0,0,0,0,0,0,0,1,0,0};
    const int kwb[NSEG] = {0,0,0,0,0,0,256,0,0,0,256};
    const int kre[NSEG] = {39,256,256,256,256,256,39,256,256,256,27};
    const int off[NSEG] = {OFF_W0,OFF_W1,OFF_W2,OFF_W3,OFF_W4,OFF_W5H,
                           OFF_W5E,OFF_W6,OFF_W7,OFF_WCH,OFF_WCE};
    const float* Wp[NSEG] = {W0,W1,W2,W3,W4,W5,W5,W6,W7,Wc,Wc};

    int gid = blockIdx.x * blockDim.x + threadIdx.x;
    if (gid >= PREP_ELEMS) return;

    int seg = 0, acc = 0;
    for (int s = 0; s < NSEG; s++) {
        const int cnt = nch[s] * ntl[s] * 32;
        if (gid < acc + cnt) { seg = s; break; }
        acc += cnt;
    }
    int rem = gid - acc;
    const int lane  = rem & 31;  rem >>= 5;
    const int ntile = rem % ntl[seg];
    const int ci    = rem / ntl[seg];
    const int tg = lane >> 2, tq = lane & 3;
    const int col = cof[seg] + ntile * 8 + tg;
    const int k0  = ci * 16;
    const float* W = Wp[seg];
    const int ld = ldw[seg], kb = kwb[seg], KR = kre[seg];

    const float wA = (k0 + 2*tq     < KR) ? W[(size_t)(kb + k0 + 2*tq    ) * ld + col] : 0.f;
    const float wB = (k0 + 2*tq + 1 < KR) ? W[(size_t)(kb + k0 + 2*tq + 1) * ld + col] : 0.f;
    const float wC = (k0 + 8 + 2*tq     < KR) ? W[(size_t)(kb + k0 + 8 + 2*tq    ) * ld + col] : 0.f;
    const float wD = (k0 + 8 + 2*tq + 1 < KR) ? W[(size_t)(kb + k0 + 8 + 2*tq + 1) * ld + col] : 0.f;
    bf16 hA,lA,hB,lB,hC,lC,hD,lD;
    bsplit(wA,hA,lA); bsplit(wB,hB,lB); bsplit(wC,hC,lC); bsplit(wD,hD,lD);

    if (is3[seg]) {
        u32* p = g_wscr + off[seg] + ci * (ntl[seg] * 128) + ntile * 128 + lane * 4;
        p[0] = pack2(hA,hB); p[1] = pack2(hC,hD);
        p[2] = pack2(lA,lB); p[3] = pack2(lC,lD);
    } else {
        u32* p = g_wscr + off[seg] + ci * (ntl[seg] * 64) + ntile * 64 + lane * 2;
        p[0] = pack2(hA,hB); p[1] = pack2(hC,hD);
    }
}

// =====================================================================
// bf16x3 accumulation: warp tile 32(M) x 64(N) -> mt=2, nt=8.
// nt processed in pairs; within a pair, term-outer ordering.
// =====================================================================
__device__ __forceinline__ void accum3x_g(
    float acc[2][8][4], const u32* __restrict__ segp, int nch,
    const bf16* __restrict__ src_hi, const bf16* __restrict__ src_lo,
    int sstr, int mbase, int n0, int tg, int tq, int lane)
{
    const uint4* wb = reinterpret_cast<const uint4*>(segp) + (n0 >> 3) * 32 + lane;
    for (int ci = 0; ci < nch; ci++) {
        const uint4* pc = wb + ci * 1024;
        const int k0 = ci * 16;
        u32 ah[2][4], al[2][4];
        #pragma unroll
        for (int mt = 0; mt < 2; mt++) {
            const int r = mbase + mt * 16 + tg;
            const bf16* ph = src_hi + r * sstr + k0 + 2 * tq;
            const bf16* pl = src_lo + r * sstr + k0 + 2 * tq;
            ah[mt][0] = *(const u32*)(ph);
            ah[mt][1] = *(const u32*)(ph + 8 * sstr);
            ah[mt][2] = *(const u32*)(ph + 8);
            ah[mt][3] = *(const u32*)(ph + 8 * sstr + 8);
            al[mt][0] = *(const u32*)(pl);
            al[mt][1] = *(const u32*)(pl + 8 * sstr);
            al[mt][2] = *(const u32*)(pl + 8);
            al[mt][3] = *(const u32*)(pl + 8 * sstr + 8);
        }
        #pragma unroll
        for (int np = 0; np < 4; np++) {           // nt pairs
            const uint4 Ba = __ldg(pc + (2 * np)     * 32);
            const uint4 Bb = __ldg(pc + (2 * np + 1) * 32);
            const u32 bhA[2] = {Ba.x, Ba.y}, blA[2] = {Ba.z, Ba.w};
            const u32 bhB[2] = {Bb.x, Bb.y}, blB[2] = {Bb.z, Bb.w};
            float* a00 = acc[0][2 * np];
            float* a10 = acc[1][2 * np];
            float* a01 = acc[0][2 * np + 1];
            float* a11 = acc[1][2 * np + 1];
            // term-outer: each accumulator revisited at stride 4
            mma16(a00, al[0], bhA); mma16(a10, al[1], bhA);
            mma16(a01, al[0], bhB); mma16(a11, al[1], bhB);
            mma16(a00, ah[0], blA); mma16(a10, ah[1], blA);
            mma16(a01, ah[0], blB); mma16(a11, ah[1], blB);
            mma16(a00, ah[0], bhA); mma16(a10, ah[1], bhA);
            mma16(a01, ah[0], bhB); mma16(a11, ah[1], bhB);
        }
    }
}

// ---- single-pass bf16, 256 cols (L7): mt=2, nt=8, uint2 frags ----
__device__ __forceinline__ void accum1x_g256(
    float acc[2][8][4], const u32* __restrict__ segp, int nch,
    const bf16* __restrict__ src_hi, int sstr,
    int mbase, int n0, int tg, int tq, int lane)
{
    const uint2* wb = reinterpret_cast<const uint2*>(segp) + (n0 >> 3) * 32 + lane;
    for (int ci = 0; ci < nch; ci++) {
        const uint2* pc = wb + ci * 1024;
        const int k0 = ci * 16;
        u32 ah[2][4];
        #pragma unroll
        for (int mt = 0; mt < 2; mt++) {
            const int r = mbase + mt * 16 + tg;
            const bf16* ph = src_hi + r * sstr + k0 + 2 * tq;
            ah[mt][0] = *(const u32*)(ph);
            ah[mt][1] = *(const u32*)(ph + 8 * sstr);
            ah[mt][2] = *(const u32*)(ph + 8);
            ah[mt][3] = *(const u32*)(ph + 8 * sstr + 8);
        }
        #pragma unroll
        for (int np = 0; np < 4; np++) {
            const uint2 Ba = __ldg(pc + (2 * np)     * 32);
            const uint2 Bb = __ldg(pc + (2 * np + 1) * 32);
            const u32 bA[2] = {Ba.x, Ba.y};
            const u32 bB[2] = {Bb.x, Bb.y};
            mma16(acc[0][2 * np],     ah[0], bA);
            mma16(acc[1][2 * np],     ah[1], bA);
            mma16(acc[0][2 * np + 1], ah[0], bB);
            mma16(acc[1][2 * np + 1], ah[1], bB);
        }
    }
}

// ---- single-pass bf16, 128 cols (head): mt=2, nt=4 ----
__device__ __forceinline__ void accum1x_g128(
    float acc[2][4][4], const u32* __restrict__ segp, int nch,
    const bf16* __restrict__ src_hi, int sstr,
    int mbase, int n0, int tg, int tq, int lane)
{
    const uint2* wb = reinterpret_cast<const uint2*>(segp) + (n0 >> 3) * 32 + lane;
    for (int ci = 0; ci < nch; ci++) {
        const uint2* pc = wb + ci * 512;
        const int k0 = ci * 16;
        u32 ah[2][4];
        #pragma unroll
        for (int mt = 0; mt < 2; mt++) {
            const int r = mbase + mt * 16 + tg;
            const bf16* ph = src_hi + r * sstr + k0 + 2 * tq;
            ah[mt][0] = *(const u32*)(ph);
            ah[mt][1] = *(const u32*)(ph + 8 * sstr);
            ah[mt][2] = *(const u32*)(ph + 8);
            ah[mt][3] = *(const u32*)(ph + 8 * sstr + 8);
        }
        #pragma unroll
        for (int np = 0; np < 2; np++) {
            const uint2 Ba = __ldg(pc + (2 * np)     * 32);
            const uint2 Bb = __ldg(pc + (2 * np + 1) * 32);
            const u32 bA[2] = {Ba.x, Ba.y};
            const u32 bB[2] = {Bb.x, Bb.y};
            mma16(acc[0][2 * np],     ah[0], bA);
            mma16(acc[1][2 * np],     ah[1], bA);
            mma16(acc[0][2 * np + 1], ah[0], bB);
            mma16(acc[1][2 * np + 1], ah[1], bB);
        }
    }
}

// ---- Epilogues ----
__device__ __forceinline__ void epilogue_256(
    float acc[2][8][4], const float* __restrict__ bg, int co,
    bf16* __restrict__ dst_hi, bf16* __restrict__ dst_lo, bool relu,
    int mbase, int n0, int tg, int tq)
{
    __syncthreads();
    #pragma unroll
    for (int nt = 0; nt < 8; nt++) {
        const int c = n0 + nt * 8 + 2 * tq;
        const float b0v = bg[co + c];
        const float b1v = bg[co + c + 1];
        #pragma unroll
        for (int mt = 0; mt < 2; mt++) {
            float v0 = acc[mt][nt][0] + b0v;
            float v1 = acc[mt][nt][1] + b1v;
            float v2 = acc[mt][nt][2] + b0v;
            float v3 = acc[mt][nt][3] + b1v;
            if (relu) {
                v0 = fmaxf(v0, 0.f); v1 = fmaxf(v1, 0.f);
                v2 = fmaxf(v2, 0.f); v3 = fmaxf(v3, 0.f);
            }
            const int r = mbase + mt * 16 + tg;
            bf16 h0, l0, h1, l1;
            bsplit(v0, h0, l0); bsplit(v1, h1, l1);
            *(u32*)(dst_hi + r * HSB + c) = pack2(h0, h1);
            *(u32*)(dst_lo + r * HSB + c) = pack2(l0, l1);
            bsplit(v2, h0, l0); bsplit(v3, h1, l1);
            *(u32*)(dst_hi + (r + 8) * HSB + c) = pack2(h0, h1);
            *(u32*)(dst_lo + (r + 8) * HSB + c) = pack2(l0, l1);
        }
    }
    __syncthreads();
}

__device__ __forceinline__ void epilogue_128(
    float acc[2][4][4], const float* __restrict__ bg,
    bf16* __restrict__ dst_hi, bf16* __restrict__ dst_lo,
    int mbase, int n0, int tg, int tq)
{
    __syncthreads();
    #pragma unroll
    for (int nt = 0; nt < 4; nt++) {
        const int c = n0 + nt * 8 + 2 * tq;
        const float b0v = bg[c];
        const float b1v = bg[c + 1];
        #pragma unroll
        for (int mt = 0; mt < 2; mt++) {
            float v0 = fmaxf(acc[mt][nt][0] + b0v, 0.f);
            float v1 = fmaxf(acc[mt][nt][1] + b1v, 0.f);
            float v2 = fmaxf(acc[mt][nt][2] + b0v, 0.f);
            float v3 = fmaxf(acc[mt][nt][3] + b1v, 0.f);
            const int r = mbase + mt * 16 + tg;
            bf16 h0, l0, h1, l1;
            bsplit(v0, h0, l0); bsplit(v1, h1, l1);
            *(u32*)(dst_hi + r * HSB + c) = pack2(h0, h1);
            *(u32*)(dst_lo + r * HSB + c) = pack2(l0, l1);
            bsplit(v2, h0, l0); bsplit(v3, h1, l1);
            *(u32*)(dst_hi + (r + 8) * HSB + c) = pack2(h0, h1);
            *(u32*)(dst_lo + (r + 8) * HSB + c) = pack2(l0, l1);
        }
    }
    __syncthreads();
}

__device__ __forceinline__ void zero_acc8(float acc[2][8][4]) {
    #pragma unroll
    for (int i = 0; i < 2; i++)
        #pragma unroll
        for (int j = 0; j < 8; j++)
            #pragma unroll
            for (int k = 0; k < 4; k++) acc[i][j][k] = 0.f;
}

__global__ void __launch_bounds__(NRF_THREADS, 2) nerf_tc_kernel(
    const float* __restrict__ pts, const float* __restrict__ dirs,
    const float* __restrict__ b0, const float* __restrict__ b1,
    const float* __restrict__ b2, const float* __restrict__ b3,
    const float* __restrict__ b4, const float* __restrict__ b5,
    const float* __restrict__ b6, const float* __restrict__ b7,
    const float* __restrict__ W7, const float* __restrict__ bc,
    const float* __restrict__ Wo, const float* __restrict__ bo,
    float* __restrict__ out_color, float* __restrict__ out_sigma, int P)
{
    extern __shared__ char smc[];
    bf16* h_hi = (bf16*)smc;                    // [64][HSB]
    bf16* h_lo = h_hi + NRF_TILE * HSB;
    bf16* e_hi = h_lo + NRF_TILE * HSB;         // [64][ESB]
    bf16* e_lo = e_hi + NRF_TILE * ESB;

    const int tid  = threadIdx.x;
    const int warp = tid >> 5;
    const int lane = tid & 31;
    const int tg = lane >> 2;
    const int tq = lane & 3;
    const int mbase  = (warp >> 2) * 32;   // 2 m-groups of 32 rows
    const int n0_256 = (warp & 3) * 64;    // 4 n-groups of 64 cols
    const int n0_128 = (warp & 3) * 32;    // 4 n-groups of 32 cols
    const int base = blockIdx.x * NRF_TILE;

    // ---- xyz harmonic embedding, pre-split hi/lo ----
    if (tid < NRF_TILE) {
        const int n = base + tid;
        const float x = pts[n * 3 + 0];
        const float y = pts[n * 3 + 1];
        const float z = pts[n * 3 + 2];
        bf16* eh = e_hi + tid * ESB;
        bf16* el = e_lo + tid * ESB;
        #pragma unroll
        for (int h = 0; h < 6; h++) {
            const float f = (float)(1 << h);
            float sx, cx, sy, cy, sz, cz;
            sincosf(x * f, &sx, &cx);
            sincosf(y * f, &sy, &cy);
            sincosf(z * f, &sz, &cz);
            bf16 hh, ll;
            bsplit(sx, hh, ll); eh[0  + h] = hh; el[0  + h] = ll;
            bsplit(sy, hh, ll); eh[6  + h] = hh; el[6  + h] = ll;
            bsplit(sz, hh, ll); eh[12 + h] = hh; el[12 + h] = ll;
            bsplit(cx, hh, ll); eh[18 + h] = hh; el[18 + h] = ll;
            bsplit(cy, hh, ll); eh[24 + h] = hh; el[24 + h] = ll;
            bsplit(cz, hh, ll); eh[30 + h] = hh; el[30 + h] = ll;
        }
        bf16 hh, ll;
        bsplit(x, hh, ll); eh[36] = hh; el[36] = ll;
        bsplit(y, hh, ll); eh[37] = hh; el[37] = ll;
        bsplit(z, hh, ll); eh[38] = hh; el[38] = ll;
        const bf16 zb = __float2bfloat16_rn(0.f);
        #pragma unroll
        for (int c = 39; c < 48; c++) { eh[c] = zb; el[c] = zb; }
    }
    __syncthreads();

    float acc[2][8][4];

    // ---- L0: e(39) -> 256, ReLU ----
    zero_acc8(acc);
    accum3x_g(acc, g_wscr + OFF_W0, 3, e_hi, e_lo, ESB, mbase, n0_256, tg, tq, lane);
    epilogue_256(acc, b0, 0, h_hi, h_lo, true, mbase, n0_256, tg, tq);

    // ---- L1..L4 ----
    {
        const u32* segs[4] = {g_wscr + OFF_W1, g_wscr + OFF_W2,
                              g_wscr + OFF_W3, g_wscr + OFF_W4};
        const float* bs[4] = {b1, b2, b3, b4};
        #pragma unroll 1
        for (int l = 0; l < 4; l++) {
            zero_acc8(acc);
            accum3x_g(acc, segs[l], 16, h_hi, h_lo, HSB, mbase, n0_256, tg, tq, lane);
            epilogue_256(acc, bs[l], 0, h_hi, h_lo, true, mbase, n0_256, tg, tq);
        }
    }

    // ---- L5: [h, e] ----
    zero_acc8(acc);
    accum3x_g(acc, g_wscr + OFF_W5H, 16, h_hi, h_lo, HSB, mbase, n0_256, tg, tq, lane);
    accum3x_g(acc, g_wscr + OFF_W5E, 3,  e_hi, e_lo, ESB, mbase, n0_256, tg, tq, lane);
    epilogue_256(acc, b5, 0, h_hi, h_lo, true, mbase, n0_256, tg, tq);

    // ---- L6 ----
    zero_acc8(acc);
    accum3x_g(acc, g_wscr + OFF_W6, 16, h_hi, h_lo, HSB, mbase, n0_256, tg, tq, lane);
    epilogue_256(acc, b6, 0, h_hi, h_lo, true, mbase, n0_256, tg, tq);

    // ---- Sigma (fp32 SIMT over reconstructed h6) ----
    if (tid < NRF_TILE) {
        float s = b7[0];
        const bf16* ph = h_hi + tid * HSB;
        const bf16* pl = h_lo + tid * HSB;
        #pragma unroll 4
        for (int k = 0; k < 256; k++) {
            const float hv = __bfloat162float(ph[k]) + __bfloat162float(pl[k]);
            s = fmaf(hv, W7[k * 257], s);
        }
        out_sigma[base + tid] = fmaxf(s, 0.f);
    }

    // ---- L7 cols 1..256 (1x bf16) ----
    zero_acc8(acc);
    accum1x_g256(acc, g_wscr + OFF_W7, 16, h_hi, HSB, mbase, n0_256, tg, tq, lane);
    epilogue_256(acc, b7, 1, h_hi, h_lo, false, mbase, n0_256, tg, tq);

    // ---- dir harmonic embedding (reuses e_hi) ----
    if (tid < NRF_TILE) {
        const int n = base + tid;
        const int r = n / P;
        const float dx = dirs[r * 3 + 0];
        const float dy = dirs[r * 3 + 1];
        const float dz = dirs[r * 3 + 2];
        bf16* eh = e_hi + tid * ESB;
        #pragma unroll
        for (int h = 0; h < 4; h++) {
            const float f = (float)(1 << h);
            float sx, cx, sy, cy, sz, cz;
            sincosf(dx * f, &sx, &cx);
            sincosf(dy * f, &sy, &cy);
            sincosf(dz * f, &sz, &cz);
            eh[0  + h] = __float2bfloat16_rn(sx);
            eh[4  + h] = __float2bfloat16_rn(sy);
            eh[8  + h] = __float2bfloat16_rn(sz);
            eh[12 + h] = __float2bfloat16_rn(cx);
            eh[16 + h] = __float2bfloat16_rn(cy);
            eh[20 + h] = __float2bfloat16_rn(cz);
        }
        eh[24] = __float2bfloat16_rn(dx);
        eh[25] = __float2bfloat16_rn(dy);
        eh[26] = __float2bfloat16_rn(dz);
        const bf16 zb = __float2bfloat16_rn(0.f);
        #pragma unroll
        for (int c = 27; c < 32; c++) eh[c] = zb;
    }
    __syncthreads();

    // ---- Color head: [h7, d] -> 128, ReLU ----
    {
        float acc2[2][4][4];
        #pragma unroll
        for (int i = 0; i < 2; i++)
            #pragma unroll
            for (int j = 0; j < 4; j++)
                #pragma unroll
                for (int k = 0; k < 4; k++) acc2[i][j][k] = 0.f;
        accum1x_g128(acc2, g_wscr + OFF_WCH, 16, h_hi, HSB, mbase, n0_128, tg, tq, lane);
        accum1x_g128(acc2, g_wscr + OFF_WCE, 2,  e_hi, ESB, mbase, n0_128, tg, tq, lane);
        epilogue_128(acc2, bc, h_hi, h_lo, mbase, n0_128, tg, tq);
    }

    // ---- Output: sigmoid(h @ Wo + bo), 192 (point,channel) pairs ----
    if (tid < NRF_TILE * 3) {
        const int p = tid / 3;
        const int c = tid - p * 3;
        float s = bo[c];
        const bf16* ph = h_hi + p * HSB;
        const bf16* pl = h_lo + p * HSB;
        #pragma unroll 4
        for (int k = 0; k < 128; k++) {
            const float hv = __bfloat162float(ph[k]) + __bfloat162float(pl[k]);
            s = fmaf(hv, Wo[k * 3 + c], s);
        }
        out_color[(base + p) * 3 + c] = 1.f / (1.f + expf(-s));
    }
}

extern "C" void kernel_launch(void* const* d_in, const int* in_sizes, int n_in,
                              void* d_out, int out_size)
{
    const float* pts  = (const float*)d_in[0];
    const float* dirs = (const float*)d_in[1];
    const float* W0 = (const float*)d_in[2];   const float* b0 = (const float*)d_in[3];
    const float* W1 = (const float*)d_in[4];   const float* b1 = (const float*)d_in[5];
    const float* W2 = (const float*)d_in[6];   const float* b2 = (const float*)d_in[7];
    const float* W3 = (const float*)d_in[8];   const float* b3 = (const float*)d_in[9];
    const float* W4 = (const float*)d_in[10];  const float* b4 = (const float*)d_in[11];
    const float* W5 = (const float*)d_in[12];  const float* b5 = (const float*)d_in[13];
    const float* W6 = (const float*)d_in[14];  const float* b6 = (const float*)d_in[15];
    const float* W7 = (const float*)d_in[16];  const float* b7 = (const float*)d_in[17];
    const float* Wc = (const float*)d_in[18];  const float* bc = (const float*)d_in[19];
    const float* Wo = (const float*)d_in[20];  const float* bo = (const float*)d_in[21];

    const int N = in_sizes[0] / 3;        // 131072 points
    const int R = in_sizes[1] / 3;        // 2048 rays
    const int P = N / R;                  // 64 samples per ray

    float* out_color = (float*)d_out;               // [N,3] first (tuple order)
    float* out_sigma = out_color + (size_t)N * 3;   // [N,1] after

    prep_weights<<<(PREP_ELEMS + 255) / 256, 256>>>(
        W0, W1, W2, W3, W4, W5, W6, W7, Wc);

    const int smem_bytes = (NRF_TILE * HSB * 2 + NRF_TILE * ESB * 2)
                           * (int)sizeof(bf16);
    cudaFuncSetAttribute(nerf_tc_kernel,
                         cudaFuncAttributeMaxDynamicSharedMemorySize, smem_bytes);

    nerf_tc_kernel<<<N / NRF_TILE, NRF_THREADS, smem_bytes>>>(
        pts, dirs,
        b0, b1, b2, b3, b4, b5, b6, b7,
        W7, bc, Wo, bo,
        out_color, out_sigma, P);
}

// round 12
// speedup vs baseline: 1.7377x; 1.0580x over previous
#include <cuda_runtime.h>
#include <cuda_bf16.h>
#include <cstdint>
#include <math.h>

typedef unsigned int u32;
typedef __nv_bfloat16 bf16;

// R12: trunk activations stored in mma A-FRAGMENT layout (hi/lo bf16), so
// each chunk's A-load is one LDS.128 per (mt, array) instead of 16 LDS.32.
// Epilogue pack2(v0,v1) is already an A-fragment u32 -> writes go straight
// to frag layout. Sigma reads h6 frag-scattered; head output lands in an
// fp32 linear buffer aliasing the dead h_frag_lo. e/d stay linear.
// 256 threads, TILE=64, 2 CTAs/SM, bf16x3 trunk + 1x heads, R10 scratch.

#define NRF_THREADS 256
#define NRF_TILE    64
#define ESB 56        // e row stride in bf16
#define HOSTR 129     // head-out fp32 row stride (conflict-free)

// frag storage: u32[(ci*2+mg)*2+mt][lane][4] ; 16 chunks -> 8192 u32 = 32KB
#define FRAG_U32S 8192

// ---- scratch segment table (u32 offsets), identical to R10 ----
#define OFF_W0   0
#define OFF_W1   12288
#define OFF_W2   77824
#define OFF_W3   143360
#define OFF_W4   208896
#define OFF_W5H  274432
#define OFF_W5E  339968
#define OFF_W6   352256
#define OFF_W7   417792
#define OFF_WCH  450560
#define OFF_WCE  466944
#define SCR_TOTAL 468992
#define PREP_ELEMS 130048

__device__ __align__(16) u32 g_wscr[SCR_TOTAL];

__device__ __forceinline__ void mma16(float* d, const u32* a, const u32* b) {
    asm volatile(
        "mma.sync.aligned.m16n8k16.row.col.f32.bf16.bf16.f32 "
        "{%0,%1,%2,%3}, {%4,%5,%6,%7}, {%8,%9}, {%0,%1,%2,%3};\n"
        : "+f"(d[0]), "+f"(d[1]), "+f"(d[2]), "+f"(d[3])
        : "r"(a[0]), "r"(a[1]), "r"(a[2]), "r"(a[3]),
          "r"(b[0]), "r"(b[1]));
}

__device__ __forceinline__ u32 pack2(bf16 a, bf16 b) {
    __nv_bfloat162 p;
    p.x = a; p.y = b;
    return *reinterpret_cast<u32*>(&p);
}

__device__ __forceinline__ void bsplit(float v, bf16& h, bf16& l) {
    h = __float2bfloat16_rn(v);
    l = __float2bfloat16_rn(v - __bfloat162float(h));
}

__device__ __forceinline__ float bf_lo(u32 u) {
    return __bfloat162float(*reinterpret_cast<const bf16*>(&u));
}
__device__ __forceinline__ float bf_hi(u32 u) {
    return __bfloat162float(*(reinterpret_cast<const bf16*>(&u) + 1));
}

// =====================================================================
// Pre-pass: build B-fragment scratch (identical to R10).
// =====================================================================
#define NSEG 11
__global__ void prep_weights(
    const float* __restrict__ W0, const float* __restrict__ W1,
    const float* __restrict__ W2, const float* __restrict__ W3,
    const float* __restrict__ W4, const float* __restrict__ W5,
    const float* __restrict__ W6, const float* __restrict__ W7,
    const float* __restrict__ Wc)
{
    const int nch[NSEG] = {3,16,16,16,16,16,3,16,16,16,2};
    const int ntl[NSEG] = {32,32,32,32,32,32,32,32,32,16,16};
    const int is3[NSEG] = {1,1,1,1,1,1,1,1,0,0,0};
    const int ldw[NSEG] = {256,256,256,256,256,256,256,256,257,128,128};
    const int cof[NSEG] = {0,0,0,0,0,0,0,0,1,0,0};
    const int kwb[NSEG] = {0,0,0,0,0,0,256,0,0,0,256};
    const int kre[NSEG] = {39,256,256,256,256,256,39,256,256,256,27};
    const int off[NSEG] = {OFF_W0,OFF_W1,OFF_W2,OFF_W3,OFF_W4,OFF_W5H,
                           OFF_W5E,OFF_W6,OFF_W7,OFF_WCH,OFF_WCE};
    const float* Wp[NSEG] = {W0,W1,W2,W3,W4,W5,W5,W6,W7,Wc,Wc};

    int gid = blockIdx.x * blockDim.x + threadIdx.x;
    if (gid >= PREP_ELEMS) return;

    int seg = 0, acc = 0;
    for (int s = 0; s < NSEG; s++) {
        const int cnt = nch[s] * ntl[s] * 32;
        if (gid < acc + cnt) { seg = s; break; }
        acc += cnt;
    }
    int rem = gid - acc;
    const int lane  = rem & 31;  rem >>= 5;
    const int ntile = rem % ntl[seg];
    const int ci    = rem / ntl[seg];
    const int tg = lane >> 2, tq = lane & 3;
    const int col = cof[seg] + ntile * 8 + tg;
    const int k0  = ci * 16;
    const float* W = Wp[seg];
    const int ld = ldw[seg], kb = kwb[seg], KR = kre[seg];

    const float wA = (k0 + 2*tq     < KR) ? W[(size_t)(kb + k0 + 2*tq    ) * ld + col] : 0.f;
    const float wB = (k0 + 2*tq + 1 < KR) ? W[(size_t)(kb + k0 + 2*tq + 1) * ld + col] : 0.f;
    const float wC = (k0 + 8 + 2*tq     < KR) ? W[(size_t)(kb + k0 + 8 + 2*tq    ) * ld + col] : 0.f;
    const float wD = (k0 + 8 + 2*tq + 1 < KR) ? W[(size_t)(kb + k0 + 8 + 2*tq + 1) * ld + col] : 0.f;
    bf16 hA,lA,hB,lB,hC,lC,hD,lD;
    bsplit(wA,hA,lA); bsplit(wB,hB,lB); bsplit(wC,hC,lC); bsplit(wD,hD,lD);

    if (is3[seg]) {
        u32* p = g_wscr + off[seg] + ci * (ntl[seg] * 128) + ntile * 128 + lane * 4;
        p[0] = pack2(hA,hB); p[1] = pack2(hC,hD);
        p[2] = pack2(lA,lB); p[3] = pack2(lC,lD);
    } else {
        u32* p = g_wscr + off[seg] + ci * (ntl[seg] * 64) + ntile * 64 + lane * 2;
        p[0] = pack2(hA,hB); p[1] = pack2(hC,hD);
    }
}

// frag uint4 index for (ci, mgroup, mt) + lane
__device__ __forceinline__ int frag_u4(int ci, int mg, int mt, int lane) {
    return ((ci * 2 + mg) * 2 + mt) * 32 + lane;
}

// =====================================================================
// bf16x3 accumulation, A from FRAG layout. Warp tile 32(M) x 64(N).
// =====================================================================
__device__ __forceinline__ void accum3x_frag(
    float acc[2][8][4], const u32* __restrict__ segp, int nch,
    const uint4* __restrict__ fhi, const uint4* __restrict__ flo,
    int mg, int n0, int lane)
{
    const uint4* wb = reinterpret_cast<const uint4*>(segp) + (n0 >> 3) * 32 + lane;
    for (int ci = 0; ci < nch; ci++) {
        const uint4* pc = wb + ci * 1024;
        const uint4 AH0 = fhi[frag_u4(ci, mg, 0, lane)];
        const uint4 AH1 = fhi[frag_u4(ci, mg, 1, lane)];
        const uint4 AL0 = flo[frag_u4(ci, mg, 0, lane)];
        const uint4 AL1 = flo[frag_u4(ci, mg, 1, lane)];
        const u32 ah[2][4] = {{AH0.x, AH0.y, AH0.z, AH0.w},
                              {AH1.x, AH1.y, AH1.z, AH1.w}};
        const u32 al[2][4] = {{AL0.x, AL0.y, AL0.z, AL0.w},
                              {AL1.x, AL1.y, AL1.z, AL1.w}};
        #pragma unroll
        for (int np = 0; np < 4; np++) {
            const uint4 Ba = __ldg(pc + (2 * np)     * 32);
            const uint4 Bb = __ldg(pc + (2 * np + 1) * 32);
            const u32 bhA[2] = {Ba.x, Ba.y}, blA[2] = {Ba.z, Ba.w};
            const u32 bhB[2] = {Bb.x, Bb.y}, blB[2] = {Bb.z, Bb.w};
            float* a00 = acc[0][2 * np];
            float* a10 = acc[1][2 * np];
            float* a01 = acc[0][2 * np + 1];
            float* a11 = acc[1][2 * np + 1];
            mma16(a00, al[0], bhA); mma16(a10, al[1], bhA);
            mma16(a01, al[0], bhB); mma16(a11, al[1], bhB);
            mma16(a00, ah[0], blA); mma16(a10, ah[1], blA);
            mma16(a01, ah[0], blB); mma16(a11, ah[1], blB);
            mma16(a00, ah[0], bhA); mma16(a10, ah[1], bhA);
            mma16(a01, ah[0], bhB); mma16(a11, ah[1], bhB);
        }
    }
}

// ---- bf16x3, A from LINEAR layout (e paths: L0, L5e) ----
__device__ __forceinline__ void accum3x_lin(
    float acc[2][8][4], const u32* __restrict__ segp, int nch,
    const bf16* __restrict__ src_hi, const bf16* __restrict__ src_lo,
    int sstr, int mbase, int n0, int tg, int tq, int lane)
{
    const uint4* wb = reinterpret_cast<const uint4*>(segp) + (n0 >> 3) * 32 + lane;
    for (int ci = 0; ci < nch; ci++) {
        const uint4* pc = wb + ci * 1024;
        const int k0 = ci * 16;
        u32 ah[2][4], al[2][4];
        #pragma unroll
        for (int mt = 0; mt < 2; mt++) {
            const int r = mbase + mt * 16 + tg;
            const bf16* ph = src_hi + r * sstr + k0 + 2 * tq;
            const bf16* pl = src_lo + r * sstr + k0 + 2 * tq;
            ah[mt][0] = *(const u32*)(ph);
            ah[mt][1] = *(const u32*)(ph + 8 * sstr);
            ah[mt][2] = *(const u32*)(ph + 8);
            ah[mt][3] = *(const u32*)(ph + 8 * sstr + 8);
            al[mt][0] = *(const u32*)(pl);
            al[mt][1] = *(const u32*)(pl + 8 * sstr);
            al[mt][2] = *(const u32*)(pl + 8);
            al[mt][3] = *(const u32*)(pl + 8 * sstr + 8);
        }
        #pragma unroll
        for (int np = 0; np < 4; np++) {
            const uint4 Ba = __ldg(pc + (2 * np)     * 32);
            const uint4 Bb = __ldg(pc + (2 * np + 1) * 32);
            const u32 bhA[2] = {Ba.x, Ba.y}, blA[2] = {Ba.z, Ba.w};
            const u32 bhB[2] = {Bb.x, Bb.y}, blB[2] = {Bb.z, Bb.w};
            float* a00 = acc[0][2 * np];
            float* a10 = acc[1][2 * np];
            float* a01 = acc[0][2 * np + 1];
            float* a11 = acc[1][2 * np + 1];
            mma16(a00, al[0], bhA); mma16(a10, al[1], bhA);
            mma16(a01, al[0], bhB); mma16(a11, al[1], bhB);
            mma16(a00, ah[0], blA); mma16(a10, ah[1], blA);
            mma16(a01, ah[0], blB); mma16(a11, ah[1], blB);
            mma16(a00, ah[0], bhA); mma16(a10, ah[1], bhA);
            mma16(a01, ah[0], bhB); mma16(a11, ah[1], bhB);
        }
    }
}

// ---- single-pass bf16, 256 cols, A from frag-hi (L7) ----
__device__ __forceinline__ void accum1x_frag256(
    float acc[2][8][4], const u32* __restrict__ segp, int nch,
    const uint4* __restrict__ fhi, int mg, int n0, int lane)
{
    const uint2* wb = reinterpret_cast<const uint2*>(segp) + (n0 >> 3) * 32 + lane;
    for (int ci = 0; ci < nch; ci++) {
        const uint2* pc = wb + ci * 1024;
        const uint4 AH0 = fhi[frag_u4(ci, mg, 0, lane)];
        const uint4 AH1 = fhi[frag_u4(ci, mg, 1, lane)];
        const u32 ah[2][4] = {{AH0.x, AH0.y, AH0.z, AH0.w},
                              {AH1.x, AH1.y, AH1.z, AH1.w}};
        #pragma unroll
        for (int np = 0; np < 4; np++) {
            const uint2 Ba = __ldg(pc + (2 * np)     * 32);
            const uint2 Bb = __ldg(pc + (2 * np + 1) * 32);
            const u32 bA[2] = {Ba.x, Ba.y};
            const u32 bB[2] = {Bb.x, Bb.y};
            mma16(acc[0][2 * np],     ah[0], bA);
            mma16(acc[1][2 * np],     ah[1], bA);
            mma16(acc[0][2 * np + 1], ah[0], bB);
            mma16(acc[1][2 * np + 1], ah[1], bB);
        }
    }
}

// ---- single-pass bf16, 128 cols, A from frag-hi (head h-part) ----
__device__ __forceinline__ void accum1x_frag128(
    float acc[2][4][4], const u32* __restrict__ segp, int nch,
    const uint4* __restrict__ fhi, int mg, int n0, int lane)
{
    const uint2* wb = reinterpret_cast<const uint2*>(segp) + (n0 >> 3) * 32 + lane;
    for (int ci = 0; ci < nch; ci++) {
        const uint2* pc = wb + ci * 512;
        const uint4 AH0 = fhi[frag_u4(ci, mg, 0, lane)];
        const uint4 AH1 = fhi[frag_u4(ci, mg, 1, lane)];
        const u32 ah[2][4] = {{AH0.x, AH0.y, AH0.z, AH0.w},
                              {AH1.x, AH1.y, AH1.z, AH1.w}};
        #pragma unroll
        for (int np = 0; np < 2; np++) {
            const uint2 Ba = __ldg(pc + (2 * np)     * 32);
            const uint2 Bb = __ldg(pc + (2 * np + 1) * 32);
            const u32 bA[2] = {Ba.x, Ba.y};
            const u32 bB[2] = {Bb.x, Bb.y};
            mma16(acc[0][2 * np],     ah[0], bA);
            mma16(acc[1][2 * np],     ah[1], bA);
            mma16(acc[0][2 * np + 1], ah[0], bB);
            mma16(acc[1][2 * np + 1], ah[1], bB);
        }
    }
}

// ---- single-pass bf16, 128 cols, A from LINEAR (head d-part) ----
__device__ __forceinline__ void accum1x_lin128(
    float acc[2][4][4], const u32* __restrict__ segp, int nch,
    const bf16* __restrict__ src_hi, int sstr,
    int mbase, int n0, int tg, int tq, int lane)
{
    const uint2* wb = reinterpret_cast<const uint2*>(segp) + (n0 >> 3) * 32 + lane;
    for (int ci = 0; ci < nch; ci++) {
        const uint2* pc = wb + ci * 512;
        const int k0 = ci * 16;
        u32 ah[2][4];
        #pragma unroll
        for (int mt = 0; mt < 2; mt++) {
            const int r = mbase + mt * 16 + tg;
            const bf16* ph = src_hi + r * sstr + k0 + 2 * tq;
            ah[mt][0] = *(const u32*)(ph);
            ah[mt][1] = *(const u32*)(ph + 8 * sstr);
            ah[mt][2] = *(const u32*)(ph + 8);
            ah[mt][3] = *(const u32*)(ph + 8 * sstr + 8);
        }
        #pragma unroll
        for (int np = 0; np < 2; np++) {
            const uint2 Ba = __ldg(pc + (2 * np)     * 32);
            const uint2 Bb = __ldg(pc + (2 * np + 1) * 32);
            const u32 bA[2] = {Ba.x, Ba.y};
            const u32 bB[2] = {Bb.x, Bb.y};
            mma16(acc[0][2 * np],     ah[0], bA);
            mma16(acc[1][2 * np],     ah[1], bA);
            mma16(acc[0][2 * np + 1], ah[0], bB);
            mma16(acc[1][2 * np + 1], ah[1], bB);
        }
    }
}

// ---- Trunk epilogue: bias + optional ReLU, write FRAG hi(+lo) ----
__device__ __forceinline__ void epilogue_frag(
    float acc[2][8][4], const float* __restrict__ bg, int co,
    u32* __restrict__ fhi, u32* __restrict__ flo, bool relu, bool write_lo,
    int mg, int wq, int n0, int tg, int tq, int lane)
{
    __syncthreads();
    #pragma unroll
    for (int nt = 0; nt < 8; nt++) {
        const int c = n0 + nt * 8 + 2 * tq;
        const float b0v = bg[co + c];
        const float b1v = bg[co + c + 1];
        const int ci = wq * 4 + (nt >> 1);
        #pragma unroll
        for (int mt = 0; mt < 2; mt++) {
            float v0 = acc[mt][nt][0] + b0v;
            float v1 = acc[mt][nt][1] + b1v;
            float v2 = acc[mt][nt][2] + b0v;
            float v3 = acc[mt][nt][3] + b1v;
            if (relu) {
                v0 = fmaxf(v0, 0.f); v1 = fmaxf(v1, 0.f);
                v2 = fmaxf(v2, 0.f); v3 = fmaxf(v3, 0.f);
            }
            const int ub = (((ci * 2 + mg) * 2 + mt) * 128) + lane * 4 + (nt & 1) * 2;
            bf16 h0, l0, h1, l1, h2, l2, h3, l3;
            bsplit(v0, h0, l0); bsplit(v1, h1, l1);
            bsplit(v2, h2, l2); bsplit(v3, h3, l3);
            fhi[ub + 0] = pack2(h0, h1);   // hseg0: row r
            fhi[ub + 1] = pack2(h2, h3);   // hseg1: row r+8
            if (write_lo) {
                flo[ub + 0] = pack2(l0, l1);
                flo[ub + 1] = pack2(l2, l3);
            }
        }
    }
    __syncthreads();
}

// ---- Head epilogue: bias + ReLU, write fp32 LINEAR (stride HOSTR) ----
__device__ __forceinline__ void epilogue_head(
    float acc[2][4][4], const float* __restrict__ bg,
    float* __restrict__ hout, int mbase, int n0, int tg, int tq)
{
    __syncthreads();
    #pragma unroll
    for (int nt = 0; nt < 4; nt++) {
        const int c = n0 + nt * 8 + 2 * tq;
        const float b0v = bg[c];
        const float b1v = bg[c + 1];
        #pragma unroll
        for (int mt = 0; mt < 2; mt++) {
            const int r = mbase + mt * 16 + tg;
            hout[r * HOSTR + c]           = fmaxf(acc[mt][nt][0] + b0v, 0.f);
            hout[r * HOSTR + c + 1]       = fmaxf(acc[mt][nt][1] + b1v, 0.f);
            hout[(r + 8) * HOSTR + c]     = fmaxf(acc[mt][nt][2] + b0v, 0.f);
            hout[(r + 8) * HOSTR + c + 1] = fmaxf(acc[mt][nt][3] + b1v, 0.f);
        }
    }
    __syncthreads();
}

__device__ __forceinline__ void zero_acc8(float acc[2][8][4]) {
    #pragma unroll
    for (int i = 0; i < 2; i++)
        #pragma unroll
        for (int j = 0; j < 8; j++)
            #pragma unroll
            for (int k = 0; k < 4; k++) acc[i][j][k] = 0.f;
}

__global__ void __launch_bounds__(NRF_THREADS, 2) nerf_tc_kernel(
    const float* __restrict__ pts, const float* __restrict__ dirs,
    const float* __restrict__ b0, const float* __restrict__ b1,
    const float* __restrict__ b2, const float* __restrict__ b3,
    const float* __restrict__ b4, const float* __restrict__ b5,
    const float* __restrict__ b6, const float* __restrict__ b7,
    const float* __restrict__ W7, const float* __restrict__ bc,
    const float* __restrict__ Wo, const float* __restrict__ bo,
    float* __restrict__ out_color, float* __restrict__ out_sigma, int P)
{
    extern __shared__ char smc[];
    u32*  fhi  = (u32*)smc;                          // 32768 B frag hi
    u32*  flo  = fhi + FRAG_U32S;                    // 33024 B union: frag lo / head fp32
    float* hout = (float*)flo;                       // aliases flo (flo dead post-L7)
    bf16* e_hi = (bf16*)(smc + 32768 + 33024);       // [64][ESB]
    bf16* e_lo = e_hi + NRF_TILE * ESB;

    const int tid  = threadIdx.x;
    const int warp = tid >> 5;
    const int lane = tid & 31;
    const int tg = lane >> 2;
    const int tq = lane & 3;
    const int mg = warp >> 2;              // m-group (rows mg*32..mg*32+31)
    const int wq = warp & 3;               // n-quad
    const int mbase  = mg * 32;
    const int n0_256 = wq * 64;
    const int n0_128 = wq * 32;
    const int base = blockIdx.x * NRF_TILE;
    const uint4* fhi4 = reinterpret_cast<const uint4*>(fhi);
    const uint4* flo4 = reinterpret_cast<const uint4*>(flo);

    // ---- xyz harmonic embedding, linear pre-split hi/lo ----
    if (tid < NRF_TILE) {
        const int n = base + tid;
        const float x = pts[n * 3 + 0];
        const float y = pts[n * 3 + 1];
        const float z = pts[n * 3 + 2];
        bf16* eh = e_hi + tid * ESB;
        bf16* el = e_lo + tid * ESB;
        #pragma unroll
        for (int h = 0; h < 6; h++) {
            const float f = (float)(1 << h);
            float sx, cx, sy, cy, sz, cz;
            sincosf(x * f, &sx, &cx);
            sincosf(y * f, &sy, &cy);
            sincosf(z * f, &sz, &cz);
            bf16 hh, ll;
            bsplit(sx, hh, ll); eh[0  + h] = hh; el[0  + h] = ll;
            bsplit(sy, hh, ll); eh[6  + h] = hh; el[6  + h] = ll;
            bsplit(sz, hh, ll); eh[12 + h] = hh; el[12 + h] = ll;
            bsplit(cx, hh, ll); eh[18 + h] = hh; el[18 + h] = ll;
            bsplit(cy, hh, ll); eh[24 + h] = hh; el[24 + h] = ll;
            bsplit(cz, hh, ll); eh[30 + h] = hh; el[30 + h] = ll;
        }
        bf16 hh, ll;
        bsplit(x, hh, ll); eh[36] = hh; el[36] = ll;
        bsplit(y, hh, ll); eh[37] = hh; el[37] = ll;
        bsplit(z, hh, ll); eh[38] = hh; el[38] = ll;
        const bf16 zb = __float2bfloat16_rn(0.f);
        #pragma unroll
        for (int c = 39; c < 48; c++) { eh[c] = zb; el[c] = zb; }
    }
    __syncthreads();

    float acc[2][8][4];

    // ---- L0: e(39) -> 256, ReLU (linear A) ----
    zero_acc8(acc);
    accum3x_lin(acc, g_wscr + OFF_W0, 3, e_hi, e_lo, ESB, mbase, n0_256, tg, tq, lane);
    epilogue_frag(acc, b0, 0, fhi, flo, true, true, mg, wq, n0_256, tg, tq, lane);

    // ---- L1..L4 (frag A) ----
    {
        const u32* segs[4] = {g_wscr + OFF_W1, g_wscr + OFF_W2,
                              g_wscr + OFF_W3, g_wscr + OFF_W4};
        const float* bs[4] = {b1, b2, b3, b4};
        #pragma unroll 1
        for (int l = 0; l < 4; l++) {
            zero_acc8(acc);
            accum3x_frag(acc, segs[l], 16, fhi4, flo4, mg, n0_256, lane);
            epilogue_frag(acc, bs[l], 0, fhi, flo, true, true, mg, wq, n0_256, tg, tq, lane);
        }
    }

    // ---- L5: [h(frag), e(linear)] ----
    zero_acc8(acc);
    accum3x_frag(acc, g_wscr + OFF_W5H, 16, fhi4, flo4, mg, n0_256, lane);
    accum3x_lin(acc, g_wscr + OFF_W5E, 3, e_hi, e_lo, ESB, mbase, n0_256, tg, tq, lane);
    epilogue_frag(acc, b5, 0, fhi, flo, true, true, mg, wq, n0_256, tg, tq, lane);

    // ---- L6 (frag A) ----
    zero_acc8(acc);
    accum3x_frag(acc, g_wscr + OFF_W6, 16, fhi4, flo4, mg, n0_256, lane);
    epilogue_frag(acc, b6, 0, fhi, flo, true, true, mg, wq, n0_256, tg, tq, lane);

    // ---- Sigma: fp32 dot over h6 read from frag layout ----
    if (tid < NRF_TILE) {
        const int row = tid;
        const int smg = row >> 5, smt = (row >> 4) & 1;
        const int shseg = (row >> 3) & 1, stg = row & 7;
        float s = b7[0];
        #pragma unroll 4
        for (int k = 0; k < 256; k += 2) {
            const int cp = k >> 1;
            const int ci = cp >> 3, cq = cp & 7;
            const int half = cq >> 2, tqd = cq & 3;
            const int idx = ((ci * 2 + smg) * 2 + smt) * 128
                          + (stg * 4 + tqd) * 4 + half * 2 + shseg;
            const u32 uh = fhi[idx];
            const u32 ul = flo[idx];
            s = fmaf(bf_lo(uh) + bf_lo(ul), W7[(size_t)k * 257], s);
            s = fmaf(bf_hi(uh) + bf_hi(ul), W7[(size_t)(k + 1) * 257], s);
        }
        out_sigma[base + tid] = fmaxf(s, 0.f);
    }
    // (sigma reads complete before L7 epilogue's writes: its leading barrier)

    // ---- L7 cols 1..256 (1x, frag-hi A; output hi-only frags) ----
    zero_acc8(acc);
    accum1x_frag256(acc, g_wscr + OFF_W7, 16, fhi4, mg, n0_256, lane);
    epilogue_frag(acc, b7, 1, fhi, flo, false, false, mg, wq, n0_256, tg, tq, lane);

    // ---- dir harmonic embedding into e_hi (linear) ----
    if (tid < NRF_TILE) {
        const int n = base + tid;
        const int r = n / P;
        const float dx = dirs[r * 3 + 0];
        const float dy = dirs[r * 3 + 1];
        const float dz = dirs[r * 3 + 2];
        bf16* eh = e_hi + tid * ESB;
        #pragma unroll
        for (int h = 0; h < 4; h++) {
            const float f = (float)(1 << h);
            float sx, cx, sy, cy, sz, cz;
            sincosf(dx * f, &sx, &cx);
            sincosf(dy * f, &sy, &cy);
            sincosf(dz * f, &sz, &cz);
            eh[0  + h] = __float2bfloat16_rn(sx);
            eh[4  + h] = __float2bfloat16_rn(sy);
            eh[8  + h] = __float2bfloat16_rn(sz);
            eh[12 + h] = __float2bfloat16_rn(cx);
            eh[16 + h] = __float2bfloat16_rn(cy);
            eh[20 + h] = __float2bfloat16_rn(cz);
        }
        eh[24] = __float2bfloat16_rn(dx);
        eh[25] = __float2bfloat16_rn(dy);
        eh[26] = __float2bfloat16_rn(dz);
        const bf16 zb = __float2bfloat16_rn(0.f);
        #pragma unroll
        for (int c = 27; c < 32; c++) eh[c] = zb;
    }
    __syncthreads();

    // ---- Color head: [h7(frag-hi), d(linear)] -> 128, ReLU, fp32 out ----
    {
        float acc2[2][4][4];
        #pragma unroll
        for (int i = 0; i < 2; i++)
            #pragma unroll
            for (int j = 0; j < 4; j++)
                #pragma unroll
                for (int k = 0; k < 4; k++) acc2[i][j][k] = 0.f;
        accum1x_frag128(acc2, g_wscr + OFF_WCH, 16, fhi4, mg, n0_128, lane);
        accum1x_lin128(acc2, g_wscr + OFF_WCE, 2, e_hi, ESB, mbase, n0_128, tg, tq, lane);
        epilogue_head(acc2, bc, hout, mbase, n0_128, tg, tq);
    }

    // ---- Output: sigmoid(hout @ Wo + bo), 192 (point,channel) pairs ----
    if (tid < NRF_TILE * 3) {
        const int p = tid / 3;
        const int c = tid - p * 3;
        float s = bo[c];
        const float* hp = hout + p * HOSTR;
        #pragma unroll 4
        for (int k = 0; k < 128; k++)
            s = fmaf(hp[k], Wo[k * 3 + c], s);
        out_color[(base + p) * 3 + c] = 1.f / (1.f + expf(-s));
    }
}

extern "C" void kernel_launch(void* const* d_in, const int* in_sizes, int n_in,
                              void* d_out, int out_size)
{
    const float* pts  = (const float*)d_in[0];
    const float* dirs = (const float*)d_in[1];
    const float* W0 = (const float*)d_in[2];   const float* b0 = (const float*)d_in[3];
    const float* W1 = (const float*)d_in[4];   const float* b1 = (const float*)d_in[5];
    const float* W2 = (const float*)d_in[6];   const float* b2 = (const float*)d_in[7];
    const float* W3 = (const float*)d_in[8];   const float* b3 = (const float*)d_in[9];
    const float* W4 = (const float*)d_in[10];  const float* b4 = (const float*)d_in[11];
    const float* W5 = (const float*)d_in[12];  const float* b5 = (const float*)d_in[13];
    const float* W6 = (const float*)d_in[14];  const float* b6 = (const float*)d_in[15];
    const float* W7 = (const float*)d_in[16];  const float* b7 = (const float*)d_in[17];
    const float* Wc = (const float*)d_in[18];  const float* bc = (const float*)d_in[19];
    const float* Wo = (const float*)d_in[20];  const float* bo = (const float*)d_in[21];

    const int N = in_sizes[0] / 3;        // 131072 points
    const int R = in_sizes[1] / 3;        // 2048 rays
    const int P = N / R;                  // 64 samples per ray

    float* out_color = (float*)d_out;               // [N,3] first (tuple order)
    float* out_sigma = out_color + (size_t)N * 3;   // [N,1] after

    prep_weights<<<(PREP_ELEMS + 255) / 256, 256>>>(
        W0, W1, W2, W3, W4, W5, W6, W7, Wc);

    // smem: fhi 32768 + union(flo/hout) 33024 + e_hi 7168 + e_lo 7168
    const int smem_bytes = 32768 + 33024 + 2 * (NRF_TILE * ESB * (int)sizeof(bf16));
    cudaFuncSetAttribute(nerf_tc_kernel,
                         cudaFuncAttributeMaxDynamicSharedMemorySize, smem_bytes);

    nerf_tc_kernel<<<N / NRF_TILE, NRF_THREADS, smem_bytes>>>(
        pts, dirs,
        b0, b1, b2, b3, b4, b5, b6, b7,
        W7, bc, Wo, bo,
        out_color, out_sigma, P);
}